// round 4
// baseline (speedup 1.0000x reference)
#include <cuda_runtime.h>
#include <cuda_bf16.h>
#include <cstdint>

#define D     512
#define NH    8
#define HD    64
#define WN    5
#define BATCH 4
#define SEQ   4096
#define MTOT  (BATCH * SEQ)

// ---------------- scratch (static device allocations) ----------------
__device__ float         g_qkv[3ull * MTOT * D];          // q,k,v fp32
__device__ __nv_bfloat16 g_Xhi[(size_t)MTOT * D];
__device__ __nv_bfloat16 g_Xlo[(size_t)MTOT * D];
__device__ __nv_bfloat16 g_Whi[3ull * D * D];             // transposed: [n][k]
__device__ __nv_bfloat16 g_Wlo[3ull * D * D];

// ---------------- PTX helpers ----------------
__device__ __forceinline__ uint32_t smem_u32(const void* p) {
    uint32_t a;
    asm("{ .reg .u64 t; cvta.to.shared.u64 t, %1; cvt.u32.u64 %0, t; }" : "=r"(a) : "l"(p));
    return a;
}
__device__ __forceinline__ void cp16(uint32_t dst, const void* src) {
    asm volatile("cp.async.cg.shared.global [%0], [%1], 16;" :: "r"(dst), "l"(src));
}
#define CP_COMMIT() asm volatile("cp.async.commit_group;" ::: "memory")
#define CP_WAIT(n)  asm volatile("cp.async.wait_group %0;" :: "n"(n) : "memory")

#define LDSM4(r, addr) \
    asm volatile("ldmatrix.sync.aligned.m8n8.x4.shared.b16 {%0,%1,%2,%3}, [%4];" \
        : "=r"((r)[0]), "=r"((r)[1]), "=r"((r)[2]), "=r"((r)[3]) : "r"(addr))

#define MMA_BF16(c, a, b) \
    asm volatile("mma.sync.aligned.m16n8k16.row.col.f32.bf16.bf16.f32 " \
        "{%0,%1,%2,%3},{%4,%5,%6,%7},{%8,%9},{%0,%1,%2,%3};" \
        : "+f"((c)[0]), "+f"((c)[1]), "+f"((c)[2]), "+f"((c)[3]) \
        : "r"((a)[0]), "r"((a)[1]), "r"((a)[2]), "r"((a)[3]), "r"((b)[0]), "r"((b)[1]))

// ---------------- bf16 hi/lo split conversion ----------------
__device__ __forceinline__ void split_bf16(float x, unsigned short& h, unsigned short& l) {
    __nv_bfloat16 hb = __float2bfloat16(x);
    __nv_bfloat16 lb = __float2bfloat16(x - __bfloat162float(hb));
    h = __bfloat16_as_ushort(hb);
    l = __bfloat16_as_ushort(lb);
}

__global__ __launch_bounds__(256) void convert_x(const float* __restrict__ X) {
    size_t i = (size_t)blockIdx.x * 256 + threadIdx.x;   // float4 index
    float4 v = reinterpret_cast<const float4*>(X)[i];
    unsigned short h0, h1, h2, h3, l0, l1, l2, l3;
    split_bf16(v.x, h0, l0); split_bf16(v.y, h1, l1);
    split_bf16(v.z, h2, l2); split_bf16(v.w, h3, l3);
    uint2 hh = make_uint2((uint32_t)h0 | ((uint32_t)h1 << 16), (uint32_t)h2 | ((uint32_t)h3 << 16));
    uint2 ll = make_uint2((uint32_t)l0 | ((uint32_t)l1 << 16), (uint32_t)l2 | ((uint32_t)l3 << 16));
    reinterpret_cast<uint2*>(g_Xhi)[i] = hh;
    reinterpret_cast<uint2*>(g_Xlo)[i] = ll;
}

__global__ __launch_bounds__(256) void convert_w(const float* __restrict__ Wq,
                                                 const float* __restrict__ Wk,
                                                 const float* __restrict__ Wv) {
    int idx = blockIdx.x * 256 + threadIdx.x;   // < 3*512*512
    int z = idx >> 18;
    int r = idx & 262143;
    int k = r >> 9;
    int n = r & 511;
    const float* W = (z == 0) ? Wq : (z == 1 ? Wk : Wv);
    float x = W[(size_t)k * D + n];
    unsigned short h, l;
    split_bf16(x, h, l);
    size_t di = (size_t)z * D * D + (size_t)n * D + k;   // transposed [n][k]
    g_Whi[di] = __ushort_as_bfloat16(h);
    g_Wlo[di] = __ushort_as_bfloat16(l);
}

// ---------------- mma.sync GEMM: g_qkv[z] = X @ W[z] + b[z] ----------------
// BM=256, BN=128, BK=32, 512 threads (16 warps, 4x4), warp tile 64x32.
#define BM 256
#define BN 128
#define BK 32
#define NKIT (D / BK)            // 16
#define PADK 40                  // row stride in bf16 (80 B rows -> conflict-free ldmatrix)
#define A_TILE_B (BM * PADK * 2)             // 20480
#define B_TILE_B (BN * PADK * 2)             // 10240
#define SOFF_AHI 0
#define SOFF_ALO (A_TILE_B)
#define SOFF_BHI (2 * A_TILE_B)
#define SOFF_BLO (2 * A_TILE_B + B_TILE_B)
#define STAGE_BYTES (2 * A_TILE_B + 2 * B_TILE_B)   // 61440
#define GEMM_SMEM (2 * STAGE_BYTES)                 // 122880

__device__ __forceinline__ void load_stage(
    uint32_t sb, int stage, int m0, int n0, int kc,
    const __nv_bfloat16* __restrict__ Wh, const __nv_bfloat16* __restrict__ Wl, int tid)
{
    const uint32_t base = sb + stage * STAGE_BYTES;
    // A: 256 rows x 4 16B-chunks (hi+lo) = 2048 cp16, 512 threads -> 2 iters
#pragma unroll
    for (int p = 0; p < 2; ++p) {
        const int q = tid + p * 512;
        const int r = q >> 2, c = q & 3;
        const uint32_t doff = (uint32_t)(r * PADK + c * 8) * 2;
        const size_t asrc = (size_t)(m0 + r) * D + kc + c * 8;
        cp16(base + SOFF_AHI + doff, g_Xhi + asrc);
        cp16(base + SOFF_ALO + doff, g_Xlo + asrc);
    }
    // B: 128 rows x 4 chunks (hi+lo) = 1024 cp16 -> 1 iter
    {
        const int r = tid >> 2, c = tid & 3;
        const uint32_t doff = (uint32_t)(r * PADK + c * 8) * 2;
        const size_t bsrc = (size_t)(n0 + r) * D + kc + c * 8;
        cp16(base + SOFF_BHI + doff, Wh + bsrc);
        cp16(base + SOFF_BLO + doff, Wl + bsrc);
    }
}

__global__ __launch_bounds__(512) void qkv_gemm_mma(
    const float* __restrict__ bq, const float* __restrict__ bk, const float* __restrict__ bv)
{
    extern __shared__ char smem[];
    const uint32_t sb = smem_u32(smem);

    const int tid = threadIdx.x;
    const int wid = tid >> 5;
    const int lane = tid & 31;
    const int warp_m = wid >> 2;      // 0..3
    const int warp_n = wid & 3;       // 0..3

    const int m0 = blockIdx.x * BM;
    const int n0 = blockIdx.y * BN;
    const int z = blockIdx.z;

    const __nv_bfloat16* Wh = g_Whi + (size_t)z * D * D;
    const __nv_bfloat16* Wl = g_Wlo + (size_t)z * D * D;
    float* O = g_qkv + (size_t)z * MTOT * D;
    const float* bias = (z == 0) ? bq : (z == 1 ? bk : bv);

    float acc[4][4][4];
#pragma unroll
    for (int i = 0; i < 4; i++)
#pragma unroll
        for (int j = 0; j < 4; j++)
#pragma unroll
            for (int e = 0; e < 4; e++) acc[i][j][e] = 0.f;

    load_stage(sb, 0, m0, n0, 0, Wh, Wl, tid);
    CP_COMMIT();

    // precomputed fragment addresses (offsets within a stage)
    const int a_row = warp_m * 64 + (lane & 15);
    const int a_colb = ((lane >> 4) << 3);
    const int b_row0 = warp_n * 32 + ((lane >> 4) << 3) + (lane & 7);
    const int b_colb = (((lane >> 3) & 1) << 3);

    for (int kt = 0; kt < NKIT; ++kt) {
        const int buf = kt & 1;
        if (kt + 1 < NKIT) {
            load_stage(sb, buf ^ 1, m0, n0, (kt + 1) * BK, Wh, Wl, tid);
            CP_COMMIT();
            CP_WAIT(1);
        } else {
            CP_WAIT(0);
        }
        __syncthreads();

        const uint32_t stg = sb + buf * STAGE_BYTES;
#pragma unroll
        for (int ks = 0; ks < 2; ++ks) {
            // B fragments first (persist across i loop)
            uint32_t bh[4][2], bl[4][2];
#pragma unroll
            for (int j2 = 0; j2 < 2; ++j2) {
                const int nr = b_row0 + j2 * 16;
                const uint32_t off = (uint32_t)(nr * PADK + ks * 16 + b_colb) * 2;
                uint32_t t[4];
                LDSM4(t, stg + SOFF_BHI + off);
                bh[2 * j2][0] = t[0]; bh[2 * j2][1] = t[1];
                bh[2 * j2 + 1][0] = t[2]; bh[2 * j2 + 1][1] = t[3];
                LDSM4(t, stg + SOFF_BLO + off);
                bl[2 * j2][0] = t[0]; bl[2 * j2][1] = t[1];
                bl[2 * j2 + 1][0] = t[2]; bl[2 * j2 + 1][1] = t[3];
            }
            // A fragments per i (short live range)
#pragma unroll
            for (int i = 0; i < 4; ++i) {
                uint32_t ah[4], al[4];
                const uint32_t off = (uint32_t)((a_row + i * 16) * PADK + ks * 16 + a_colb) * 2;
                LDSM4(ah, stg + SOFF_AHI + off);
                LDSM4(al, stg + SOFF_ALO + off);
#pragma unroll
                for (int j = 0; j < 4; ++j) {
                    MMA_BF16(acc[i][j], ah, bh[j]);   // hi*hi
                    MMA_BF16(acc[i][j], ah, bl[j]);   // hi*lo
                    MMA_BF16(acc[i][j], al, bh[j]);   // lo*hi
                }
            }
        }
        __syncthreads();
    }

    // ---- epilogue: direct STG with bias ----
#pragma unroll
    for (int j = 0; j < 4; ++j) {
        const int ncol = n0 + warp_n * 32 + j * 8 + (lane & 3) * 2;
        const float2 bb = *reinterpret_cast<const float2*>(bias + ncol);
#pragma unroll
        for (int i = 0; i < 4; ++i) {
            const int row0 = m0 + warp_m * 64 + i * 16 + (lane >> 2);
            float2 v0 = make_float2(acc[i][j][0] + bb.x, acc[i][j][1] + bb.y);
            float2 v1 = make_float2(acc[i][j][2] + bb.x, acc[i][j][3] + bb.y);
            *reinterpret_cast<float2*>(O + (size_t)row0 * D + ncol) = v0;
            *reinterpret_cast<float2*>(O + (size_t)(row0 + 8) * D + ncol) = v1;
        }
    }
}

// ---------------- attention (unchanged) ----------------
__global__ __launch_bounds__(256) void attn_kernel(
    const float* __restrict__ Er,
    const int*   __restrict__ layer_p,
    float* __restrict__ out,
    float* __restrict__ attn_out)
{
    const int gwarp = (int)((blockIdx.x * blockDim.x + threadIdx.x) >> 5);
    const int lane  = threadIdx.x & 31;
    if (gwarp >= BATCH * NH * SEQ) return;

    const int t = gwarp & (SEQ - 1);
    const int h = (gwarp >> 12) & (NH - 1);
    const int b = gwarp >> 15;

    const int dil = 1 << layer_p[0];
    const int shift_tab[8] = {0, 0, 0, 0, -2, -1, 1, 2};
    const int s = shift_tab[h];

    const float* Q  = g_qkv + ((size_t)(b * SEQ + t) * D + h * HD);
    const float* Kb = g_qkv + (size_t)MTOT * D;
    const float* Vb = g_qkv + 2ull * MTOT * D;

    const float2 q2 = reinterpret_cast<const float2*>(Q)[lane];
    const int d0 = h * HD + 2 * lane;

    int  tk[WN];
    bool valid[WN];
    float lg[WN];

#pragma unroll
    for (int w = 0; w < WN; w++) {
        const int tt = t + dil * (s + w - 2);
        const bool ok = (tt >= 0) && (tt < SEQ);
        tk[w] = tt;
        valid[w] = ok;
        float qk = 0.f;
        if (ok) {
            const float2 k2 = reinterpret_cast<const float2*>(
                Kb + ((size_t)(b * SEQ + tt) * D + h * HD))[lane];
            qk = q2.x * k2.x + q2.y * k2.y;
        }
        float er = q2.x * Er[(size_t)d0 * WN + w] + q2.y * Er[(size_t)(d0 + 1) * WN + w];
#pragma unroll
        for (int o = 16; o > 0; o >>= 1) {
            qk += __shfl_xor_sync(0xffffffffu, qk, o);
            er += __shfl_xor_sync(0xffffffffu, er, o);
        }
        lg[w] = ok ? (qk + er) * 0.125f : -1e30f;
    }

    float mx = lg[0];
#pragma unroll
    for (int w = 1; w < WN; w++) mx = fmaxf(mx, lg[w]);

    float p[WN];
    float sum = 0.f;
#pragma unroll
    for (int w = 0; w < WN; w++) {
        p[w] = valid[w] ? __expf(lg[w] - mx) : 0.f;
        sum += p[w];
    }
    const float inv = 1.f / sum;

    float ox = 0.f, oy = 0.f;
#pragma unroll
    for (int w = 0; w < WN; w++) {
        if (valid[w]) {
            const float a = p[w] * inv;
            const float2 v2 = reinterpret_cast<const float2*>(
                Vb + ((size_t)(b * SEQ + tk[w]) * D + h * HD))[lane];
            ox = fmaf(a, v2.x, ox);
            oy = fmaf(a, v2.y, oy);
        }
    }
    reinterpret_cast<float2*>(out + ((size_t)(b * SEQ + t) * D + h * HD))[lane] =
        make_float2(ox, oy);

    if (attn_out != nullptr && lane < WN) {
        float a = p[0];
        if (lane == 1) a = p[1];
        else if (lane == 2) a = p[2];
        else if (lane == 3) a = p[3];
        else if (lane == 4) a = p[4];
        attn_out[((size_t)((b * NH + h) * SEQ + t)) * WN + lane] = a * inv;
    }
}

// ---------------------------------------------------------------------------
extern "C" void kernel_launch(void* const* d_in, const int* in_sizes, int n_in,
                              void* d_out, int out_size)
{
    (void)in_sizes; (void)n_in;
    const float* X  = (const float*)d_in[0];
    const float* Wq = (const float*)d_in[1];
    const float* bq = (const float*)d_in[2];
    const float* Wk = (const float*)d_in[3];
    const float* bk = (const float*)d_in[4];
    const float* Wv = (const float*)d_in[5];
    const float* bv = (const float*)d_in[6];
    const float* Er = (const float*)d_in[7];
    const int* layer = (const int*)d_in[8];

    float* out = (float*)d_out;
    float* attn_out = nullptr;
    const long long OUTN = (long long)MTOT * D;
    const long long ATTN = (long long)BATCH * NH * SEQ * WN;
    if ((long long)out_size >= OUTN + ATTN) attn_out = out + OUTN;

    static bool attr_set = false;
    if (!attr_set) {
        cudaFuncSetAttribute(qkv_gemm_mma, cudaFuncAttributeMaxDynamicSharedMemorySize, GEMM_SMEM);
        attr_set = true;
    }

    convert_x<<<(MTOT * D / 4) / 256, 256>>>(X);
    convert_w<<<(3 * D * D) / 256, 256>>>(Wq, Wk, Wv);

    dim3 grid(MTOT / BM, D / BN, 3);
    qkv_gemm_mma<<<grid, 512, GEMM_SMEM>>>(bq, bk, bv);

    const int warps = BATCH * NH * SEQ;
    const int blocks = (warps * 32 + 255) / 256;
    attn_kernel<<<blocks, 256>>>(Er, layer, out, attn_out);
}

// round 5
// speedup vs baseline: 1.0917x; 1.0917x over previous
#include <cuda_runtime.h>
#include <cuda_bf16.h>
#include <cstdint>

#define D     512
#define NH    8
#define HD    64
#define WN    5
#define BATCH 4
#define SEQ   4096
#define MTOT  (BATCH * SEQ)

// ---------------- scratch (static device allocations) ----------------
__device__ float         g_qkv[3ull * MTOT * D];          // q,k,v fp32
__device__ __nv_bfloat16 g_Xhi[(size_t)MTOT * D];
__device__ __nv_bfloat16 g_Xlo[(size_t)MTOT * D];
__device__ __nv_bfloat16 g_Whi[3ull * D * D];             // transposed: [n][k]
__device__ __nv_bfloat16 g_Wlo[3ull * D * D];

// ---------------- PTX helpers ----------------
__device__ __forceinline__ uint32_t smem_u32(const void* p) {
    uint32_t a;
    asm("{ .reg .u64 t; cvta.to.shared.u64 t, %1; cvt.u32.u64 %0, t; }" : "=r"(a) : "l"(p));
    return a;
}
__device__ __forceinline__ void cp16(uint32_t dst, const void* src) {
    asm volatile("cp.async.cg.shared.global [%0], [%1], 16;" :: "r"(dst), "l"(src));
}
#define CP_COMMIT() asm volatile("cp.async.commit_group;" ::: "memory")
#define CP_WAIT(n)  asm volatile("cp.async.wait_group %0;" :: "n"(n) : "memory")

#define LDSM4(r, addr) \
    asm volatile("ldmatrix.sync.aligned.m8n8.x4.shared.b16 {%0,%1,%2,%3}, [%4];" \
        : "=r"((r)[0]), "=r"((r)[1]), "=r"((r)[2]), "=r"((r)[3]) : "r"(addr))

#define MMA_BF16(c, a, b) \
    asm volatile("mma.sync.aligned.m16n8k16.row.col.f32.bf16.bf16.f32 " \
        "{%0,%1,%2,%3},{%4,%5,%6,%7},{%8,%9},{%0,%1,%2,%3};" \
        : "+f"((c)[0]), "+f"((c)[1]), "+f"((c)[2]), "+f"((c)[3]) \
        : "r"((a)[0]), "r"((a)[1]), "r"((a)[2]), "r"((a)[3]), "r"((b)[0]), "r"((b)[1]))

// ---------------- bf16 hi/lo split conversion ----------------
__device__ __forceinline__ void split_bf16(float x, unsigned short& h, unsigned short& l) {
    __nv_bfloat16 hb = __float2bfloat16(x);
    __nv_bfloat16 lb = __float2bfloat16(x - __bfloat162float(hb));
    h = __bfloat16_as_ushort(hb);
    l = __bfloat16_as_ushort(lb);
}

__global__ __launch_bounds__(256) void convert_x(const float* __restrict__ X) {
    size_t i = (size_t)blockIdx.x * 256 + threadIdx.x;   // float4 index
    float4 v = reinterpret_cast<const float4*>(X)[i];
    unsigned short h0, h1, h2, h3, l0, l1, l2, l3;
    split_bf16(v.x, h0, l0); split_bf16(v.y, h1, l1);
    split_bf16(v.z, h2, l2); split_bf16(v.w, h3, l3);
    uint2 hh = make_uint2((uint32_t)h0 | ((uint32_t)h1 << 16), (uint32_t)h2 | ((uint32_t)h3 << 16));
    uint2 ll = make_uint2((uint32_t)l0 | ((uint32_t)l1 << 16), (uint32_t)l2 | ((uint32_t)l3 << 16));
    reinterpret_cast<uint2*>(g_Xhi)[i] = hh;
    reinterpret_cast<uint2*>(g_Xlo)[i] = ll;
}

__global__ __launch_bounds__(256) void convert_w(const float* __restrict__ Wq,
                                                 const float* __restrict__ Wk,
                                                 const float* __restrict__ Wv) {
    int idx = blockIdx.x * 256 + threadIdx.x;   // < 3*512*512
    int z = idx >> 18;
    int r = idx & 262143;
    int k = r >> 9;
    int n = r & 511;
    const float* W = (z == 0) ? Wq : (z == 1 ? Wk : Wv);
    float x = W[(size_t)k * D + n];
    unsigned short h, l;
    split_bf16(x, h, l);
    size_t di = (size_t)z * D * D + (size_t)n * D + k;   // transposed [n][k]
    g_Whi[di] = __ushort_as_bfloat16(h);
    g_Wlo[di] = __ushort_as_bfloat16(l);
}

// ---------------- mma.sync GEMM: g_qkv[z] = X @ W[z] + b[z] ----------------
// BM=128, BN=128, BK=32, 256 threads (8 warps, 2x4), warp tile 64x32.
// __launch_bounds__(256, 2): cap regs at 128 so 2 CTAs (16 warps) co-reside.
#define BM 128
#define BN 128
#define BK 32
#define NKIT (D / BK)            // 16
#define PADK 40                  // row stride in bf16 (80 B rows -> conflict-free ldmatrix)
#define TILE_BYTES (128 * PADK * 2)          // 10240
#define SOFF_AHI 0
#define SOFF_ALO (1 * TILE_BYTES)
#define SOFF_BHI (2 * TILE_BYTES)
#define SOFF_BLO (3 * TILE_BYTES)
#define STAGE_BYTES (4 * TILE_BYTES)         // 40960
#define GEMM_SMEM (2 * STAGE_BYTES)          // 81920

__device__ __forceinline__ void load_stage(
    uint32_t sb, int stage, int m0, int n0, int kc,
    const __nv_bfloat16* __restrict__ Wh, const __nv_bfloat16* __restrict__ Wl, int tid)
{
    const uint32_t base = sb + stage * STAGE_BYTES;
#pragma unroll
    for (int p = 0; p < 2; ++p) {
        const int q = tid + p * 256;
        const int r = q >> 2, c = q & 3;
        const uint32_t doff = (uint32_t)(r * PADK + c * 8) * 2;
        const size_t asrc = (size_t)(m0 + r) * D + kc + c * 8;
        cp16(base + SOFF_AHI + doff, g_Xhi + asrc);
        cp16(base + SOFF_ALO + doff, g_Xlo + asrc);
        const size_t bsrc = (size_t)(n0 + r) * D + kc + c * 8;
        cp16(base + SOFF_BHI + doff, Wh + bsrc);
        cp16(base + SOFF_BLO + doff, Wl + bsrc);
    }
}

__global__ __launch_bounds__(256, 2) void qkv_gemm_mma(
    const float* __restrict__ bq, const float* __restrict__ bk, const float* __restrict__ bv)
{
    extern __shared__ char smem[];
    const uint32_t sb = smem_u32(smem);

    const int tid = threadIdx.x;
    const int wid = tid >> 5;
    const int lane = tid & 31;
    const int warp_m = wid >> 2;      // 0..1
    const int warp_n = wid & 3;       // 0..3

    const int m0 = blockIdx.x * BM;
    const int n0 = blockIdx.y * BN;
    const int z = blockIdx.z;

    const __nv_bfloat16* Wh = g_Whi + (size_t)z * D * D;
    const __nv_bfloat16* Wl = g_Wlo + (size_t)z * D * D;
    float* O = g_qkv + (size_t)z * MTOT * D;
    const float* bias = (z == 0) ? bq : (z == 1 ? bk : bv);

    float acc[4][4][4];
#pragma unroll
    for (int i = 0; i < 4; i++)
#pragma unroll
        for (int j = 0; j < 4; j++)
#pragma unroll
            for (int e = 0; e < 4; e++) acc[i][j][e] = 0.f;

    load_stage(sb, 0, m0, n0, 0, Wh, Wl, tid);
    CP_COMMIT();

    const int a_row = warp_m * 64 + (lane & 15);
    const int a_colb = ((lane >> 4) << 3);
    const int b_row0 = warp_n * 32 + ((lane >> 4) << 3) + (lane & 7);
    const int b_colb = (((lane >> 3) & 1) << 3);

    for (int kt = 0; kt < NKIT; ++kt) {
        const int buf = kt & 1;
        if (kt + 1 < NKIT) {
            load_stage(sb, buf ^ 1, m0, n0, (kt + 1) * BK, Wh, Wl, tid);
            CP_COMMIT();
            CP_WAIT(1);
        } else {
            CP_WAIT(0);
        }
        __syncthreads();

        const uint32_t stg = sb + buf * STAGE_BYTES;
#pragma unroll
        for (int ks = 0; ks < 2; ++ks) {
            // B fragments (persist across i loop): 16 regs
            uint32_t bh[4][2], bl[4][2];
#pragma unroll
            for (int j2 = 0; j2 < 2; ++j2) {
                const int nr = b_row0 + j2 * 16;
                const uint32_t off = (uint32_t)(nr * PADK + ks * 16 + b_colb) * 2;
                uint32_t t[4];
                LDSM4(t, stg + SOFF_BHI + off);
                bh[2 * j2][0] = t[0]; bh[2 * j2][1] = t[1];
                bh[2 * j2 + 1][0] = t[2]; bh[2 * j2 + 1][1] = t[3];
                LDSM4(t, stg + SOFF_BLO + off);
                bl[2 * j2][0] = t[0]; bl[2 * j2][1] = t[1];
                bl[2 * j2 + 1][0] = t[2]; bl[2 * j2 + 1][1] = t[3];
            }
            // A fragments streamed per i: 8 regs live
#pragma unroll
            for (int i = 0; i < 4; ++i) {
                uint32_t ah[4], al[4];
                const uint32_t off = (uint32_t)((a_row + i * 16) * PADK + ks * 16 + a_colb) * 2;
                LDSM4(ah, stg + SOFF_AHI + off);
                LDSM4(al, stg + SOFF_ALO + off);
#pragma unroll
                for (int j = 0; j < 4; ++j) {
                    MMA_BF16(acc[i][j], ah, bh[j]);   // hi*hi
                    MMA_BF16(acc[i][j], ah, bl[j]);   // hi*lo
                    MMA_BF16(acc[i][j], al, bh[j]);   // lo*hi
                }
            }
        }
        __syncthreads();
    }

    // ---- epilogue: direct STG with bias ----
#pragma unroll
    for (int j = 0; j < 4; ++j) {
        const int ncol = n0 + warp_n * 32 + j * 8 + (lane & 3) * 2;
        const float2 bb = *reinterpret_cast<const float2*>(bias + ncol);
#pragma unroll
        for (int i = 0; i < 4; ++i) {
            const int row0 = m0 + warp_m * 64 + i * 16 + (lane >> 2);
            float2 v0 = make_float2(acc[i][j][0] + bb.x, acc[i][j][1] + bb.y);
            float2 v1 = make_float2(acc[i][j][2] + bb.x, acc[i][j][3] + bb.y);
            *reinterpret_cast<float2*>(O + (size_t)row0 * D + ncol) = v0;
            *reinterpret_cast<float2*>(O + (size_t)(row0 + 8) * D + ncol) = v1;
        }
    }
}

// ---------------- attention v2: 8 lanes per token, 4 tokens per warp ----------------
// Each warp owns (b, h) and 32 consecutive t (8 iterations x 4 tokens).
// Er fragment preloaded once per warp. One 3-step segmented butterfly per window.
__global__ __launch_bounds__(256) void attn_kernel(
    const float* __restrict__ Er,
    const int*   __restrict__ layer_p,
    float* __restrict__ out,
    float* __restrict__ attn_out)
{
    const int wlocal = threadIdx.x >> 5;
    const int lane = threadIdx.x & 31;
    const int gw = blockIdx.x * 8 + wlocal;
    const int li = lane & 7;       // lane within 8-lane token group
    const int g  = lane >> 3;      // token group 0..3

    const int NCH = SEQ / 32;      // t-chunks per (b,h)
    const int tc = gw & (NCH - 1);
    const int h  = (gw >> 7) & (NH - 1);
    const int b  = gw >> 10;

    const int dil = 1 << layer_p[0];
    const int shift_tab[8] = {0, 0, 0, 0, -2, -1, 1, 2};
    const int s = shift_tab[h];

    // preload Er fragment: this lane's 8 head-dims x 5 windows (t-independent)
    float erf[8][5];
#pragma unroll
    for (int k = 0; k < 8; ++k)
#pragma unroll
        for (int w = 0; w < WN; ++w)
            erf[k][w] = Er[(size_t)(h * HD + li * 8 + k) * WN + w];

    const float* Qb = g_qkv;
    const float* Kb = g_qkv + (size_t)MTOT * D;
    const float* Vb = g_qkv + 2ull * MTOT * D;
    const size_t rowbase = (size_t)b * SEQ;
    const int dcol = h * HD + li * 8;

    for (int it = 0; it < 8; ++it) {
        const int t = tc * 32 + it * 4 + g;
        const size_t qoff = (rowbase + t) * D + dcol;
        const float4 q0 = *reinterpret_cast<const float4*>(Qb + qoff);
        const float4 q1 = *reinterpret_cast<const float4*>(Qb + qoff + 4);

        float lg[WN];
        bool valid[WN];
        int tks[WN];
#pragma unroll
        for (int w = 0; w < WN; ++w) {
            const int tt = t + dil * (s + w - 2);
            const bool ok = (tt >= 0) && (tt < SEQ);
            valid[w] = ok;
            tks[w] = tt;
            // qEr partial (this lane's 8 dims)
            float part = q0.x * erf[0][w] + q0.y * erf[1][w] + q0.z * erf[2][w] + q0.w * erf[3][w]
                       + q1.x * erf[4][w] + q1.y * erf[5][w] + q1.z * erf[6][w] + q1.w * erf[7][w];
            if (ok) {
                const size_t koff = (rowbase + tt) * D + dcol;
                const float4 k0 = *reinterpret_cast<const float4*>(Kb + koff);
                const float4 k1 = *reinterpret_cast<const float4*>(Kb + koff + 4);
                part += q0.x * k0.x + q0.y * k0.y + q0.z * k0.z + q0.w * k0.w
                      + q1.x * k1.x + q1.y * k1.y + q1.z * k1.z + q1.w * k1.w;
            }
            // segmented butterfly over the 8-lane group
            part += __shfl_xor_sync(0xffffffffu, part, 1);
            part += __shfl_xor_sync(0xffffffffu, part, 2);
            part += __shfl_xor_sync(0xffffffffu, part, 4);
            lg[w] = ok ? part * 0.125f : -1e30f;
        }

        float mx = lg[0];
#pragma unroll
        for (int w = 1; w < WN; w++) mx = fmaxf(mx, lg[w]);
        float p[WN];
        float sum = 0.f;
#pragma unroll
        for (int w = 0; w < WN; w++) {
            p[w] = valid[w] ? __expf(lg[w] - mx) : 0.f;
            sum += p[w];
        }
        const float inv = 1.f / sum;

        float4 a0 = make_float4(0.f, 0.f, 0.f, 0.f);
        float4 a1 = make_float4(0.f, 0.f, 0.f, 0.f);
#pragma unroll
        for (int w = 0; w < WN; w++) {
            if (valid[w]) {
                const float a = p[w] * inv;
                const size_t voff = (rowbase + tks[w]) * D + dcol;
                const float4 v0 = *reinterpret_cast<const float4*>(Vb + voff);
                const float4 v1 = *reinterpret_cast<const float4*>(Vb + voff + 4);
                a0.x = fmaf(a, v0.x, a0.x); a0.y = fmaf(a, v0.y, a0.y);
                a0.z = fmaf(a, v0.z, a0.z); a0.w = fmaf(a, v0.w, a0.w);
                a1.x = fmaf(a, v1.x, a1.x); a1.y = fmaf(a, v1.y, a1.y);
                a1.z = fmaf(a, v1.z, a1.z); a1.w = fmaf(a, v1.w, a1.w);
            }
        }
        *reinterpret_cast<float4*>(out + qoff) = a0;
        *reinterpret_cast<float4*>(out + qoff + 4) = a1;

        if (attn_out != nullptr && li < WN) {
            float a = p[0];
            if (li == 1) a = p[1];
            else if (li == 2) a = p[2];
            else if (li == 3) a = p[3];
            else if (li == 4) a = p[4];
            attn_out[((size_t)((b * NH + h) * SEQ + t)) * WN + li] = a * inv;
        }
    }
}

// ---------------------------------------------------------------------------
extern "C" void kernel_launch(void* const* d_in, const int* in_sizes, int n_in,
                              void* d_out, int out_size)
{
    (void)in_sizes; (void)n_in;
    const float* X  = (const float*)d_in[0];
    const float* Wq = (const float*)d_in[1];
    const float* bq = (const float*)d_in[2];
    const float* Wk = (const float*)d_in[3];
    const float* bk = (const float*)d_in[4];
    const float* Wv = (const float*)d_in[5];
    const float* bv = (const float*)d_in[6];
    const float* Er = (const float*)d_in[7];
    const int* layer = (const int*)d_in[8];

    float* out = (float*)d_out;
    float* attn_out = nullptr;
    const long long OUTN = (long long)MTOT * D;
    const long long ATTN = (long long)BATCH * NH * SEQ * WN;
    if ((long long)out_size >= OUTN + ATTN) attn_out = out + OUTN;

    static bool attr_set = false;
    if (!attr_set) {
        cudaFuncSetAttribute(qkv_gemm_mma, cudaFuncAttributeMaxDynamicSharedMemorySize, GEMM_SMEM);
        attr_set = true;
    }

    convert_x<<<(MTOT * D / 4) / 256, 256>>>(X);
    convert_w<<<(3 * D * D) / 256, 256>>>(Wq, Wk, Wv);

    dim3 grid(MTOT / BM, D / BN, 3);
    qkv_gemm_mma<<<grid, 256, GEMM_SMEM>>>(bq, bk, bv);

    const int warps = BATCH * NH * (SEQ / 32);   // 4096 warps
    attn_kernel<<<warps / 8, 256>>>(Er, layer, out, attn_out);
}

// round 6
// speedup vs baseline: 1.4517x; 1.3298x over previous
#include <cuda_runtime.h>
#include <cuda_fp16.h>
#include <cstdint>

#define D     512
#define NH    8
#define HD    64
#define WN    5
#define BATCH 4
#define SEQ   4096
#define MTOT  (BATCH * SEQ)

// ---------------- scratch (static device allocations) ----------------
__device__ float  g_qkv[3ull * MTOT * D];      // q,k,v fp32
__device__ __half g_Xhi[(size_t)MTOT * D];
__device__ __half g_Xlo[(size_t)MTOT * D];
__device__ __half g_W[3ull * D * D];           // transposed: [n][k], single fp16

// ---------------- PTX helpers ----------------
__device__ __forceinline__ uint32_t smem_u32(const void* p) {
    uint32_t a;
    asm("{ .reg .u64 t; cvta.to.shared.u64 t, %1; cvt.u32.u64 %0, t; }" : "=r"(a) : "l"(p));
    return a;
}
__device__ __forceinline__ void cp16(uint32_t dst, const void* src) {
    asm volatile("cp.async.cg.shared.global [%0], [%1], 16;" :: "r"(dst), "l"(src));
}
#define CP_COMMIT() asm volatile("cp.async.commit_group;" ::: "memory")
#define CP_WAIT(n)  asm volatile("cp.async.wait_group %0;" :: "n"(n) : "memory")

#define LDSM4(r, addr) \
    asm volatile("ldmatrix.sync.aligned.m8n8.x4.shared.b16 {%0,%1,%2,%3}, [%4];" \
        : "=r"((r)[0]), "=r"((r)[1]), "=r"((r)[2]), "=r"((r)[3]) : "r"(addr))

#define MMA_F16(c, a, b) \
    asm volatile("mma.sync.aligned.m16n8k16.row.col.f32.f16.f16.f32 " \
        "{%0,%1,%2,%3},{%4,%5,%6,%7},{%8,%9},{%0,%1,%2,%3};" \
        : "+f"((c)[0]), "+f"((c)[1]), "+f"((c)[2]), "+f"((c)[3]) \
        : "r"((a)[0]), "r"((a)[1]), "r"((a)[2]), "r"((a)[3]), "r"((b)[0]), "r"((b)[1]))

// ---------------- fp16 hi/lo split conversion ----------------
__device__ __forceinline__ void split_h(float x, unsigned short& h, unsigned short& l) {
    __half hb = __float2half_rn(x);
    __half lb = __float2half_rn(x - __half2float(hb));
    h = __half_as_ushort(hb);
    l = __half_as_ushort(lb);
}

__global__ __launch_bounds__(256) void convert_x(const float* __restrict__ X) {
    size_t i = (size_t)blockIdx.x * 256 + threadIdx.x;   // float4 index
    float4 v = reinterpret_cast<const float4*>(X)[i];
    unsigned short h0, h1, h2, h3, l0, l1, l2, l3;
    split_h(v.x, h0, l0); split_h(v.y, h1, l1);
    split_h(v.z, h2, l2); split_h(v.w, h3, l3);
    uint2 hh = make_uint2((uint32_t)h0 | ((uint32_t)h1 << 16), (uint32_t)h2 | ((uint32_t)h3 << 16));
    uint2 ll = make_uint2((uint32_t)l0 | ((uint32_t)l1 << 16), (uint32_t)l2 | ((uint32_t)l3 << 16));
    reinterpret_cast<uint2*>(g_Xhi)[i] = hh;
    reinterpret_cast<uint2*>(g_Xlo)[i] = ll;
}

__global__ __launch_bounds__(256) void convert_w(const float* __restrict__ Wq,
                                                 const float* __restrict__ Wk,
                                                 const float* __restrict__ Wv) {
    int idx = blockIdx.x * 256 + threadIdx.x;   // < 3*512*512
    int z = idx >> 18;
    int r = idx & 262143;
    int k = r >> 9;
    int n = r & 511;
    const float* W = (z == 0) ? Wq : (z == 1 ? Wk : Wv);
    float x = W[(size_t)k * D + n];
    g_W[(size_t)z * D * D + (size_t)n * D + k] = __float2half_rn(x);   // transposed [n][k]
}

// ---------------- mma.sync GEMM: g_qkv[z] = X @ W[z] + b[z] ----------------
// fp16 2-pass: A split hi/lo, B single. BM=128, BN=128, BK=32, 256 threads.
#define BM 128
#define BN 128
#define BK 32
#define NKIT (D / BK)            // 16
#define PADK 40                  // row stride in fp16 (80 B rows -> conflict-free ldmatrix)
#define TILE_BYTES (128 * PADK * 2)          // 10240
#define SOFF_AHI 0
#define SOFF_ALO (1 * TILE_BYTES)
#define SOFF_B   (2 * TILE_BYTES)
#define STAGE_BYTES (3 * TILE_BYTES)         // 30720
#define GEMM_SMEM (2 * STAGE_BYTES)          // 61440

__device__ __forceinline__ void load_stage(
    uint32_t sb, int stage, int m0, int n0, int kc,
    const __half* __restrict__ W, int tid)
{
    const uint32_t base = sb + stage * STAGE_BYTES;
#pragma unroll
    for (int p = 0; p < 2; ++p) {
        const int q = tid + p * 256;
        const int r = q >> 2, c = q & 3;
        const uint32_t doff = (uint32_t)(r * PADK + c * 8) * 2;
        const size_t asrc = (size_t)(m0 + r) * D + kc + c * 8;
        cp16(base + SOFF_AHI + doff, g_Xhi + asrc);
        cp16(base + SOFF_ALO + doff, g_Xlo + asrc);
        const size_t bsrc = (size_t)(n0 + r) * D + kc + c * 8;
        cp16(base + SOFF_B + doff, W + bsrc);
    }
}

__global__ __launch_bounds__(256, 2) void qkv_gemm_mma(
    const float* __restrict__ bq, const float* __restrict__ bk, const float* __restrict__ bv)
{
    extern __shared__ char smem[];
    const uint32_t sb = smem_u32(smem);

    const int tid = threadIdx.x;
    const int wid = tid >> 5;
    const int lane = tid & 31;
    const int warp_m = wid >> 2;      // 0..1
    const int warp_n = wid & 3;       // 0..3

    const int m0 = blockIdx.x * BM;
    const int n0 = blockIdx.y * BN;
    const int z = blockIdx.z;

    const __half* W = g_W + (size_t)z * D * D;
    float* O = g_qkv + (size_t)z * MTOT * D;
    const float* bias = (z == 0) ? bq : (z == 1 ? bk : bv);

    float acc[4][4][4];
#pragma unroll
    for (int i = 0; i < 4; i++)
#pragma unroll
        for (int j = 0; j < 4; j++)
#pragma unroll
            for (int e = 0; e < 4; e++) acc[i][j][e] = 0.f;

    load_stage(sb, 0, m0, n0, 0, W, tid);
    CP_COMMIT();

    const int a_row = warp_m * 64 + (lane & 15);
    const int a_colb = ((lane >> 4) << 3);
    const int b_row0 = warp_n * 32 + ((lane >> 4) << 3) + (lane & 7);
    const int b_colb = (((lane >> 3) & 1) << 3);

    for (int kt = 0; kt < NKIT; ++kt) {
        const int buf = kt & 1;
        if (kt + 1 < NKIT) {
            load_stage(sb, buf ^ 1, m0, n0, (kt + 1) * BK, W, tid);
            CP_COMMIT();
            CP_WAIT(1);
        } else {
            CP_WAIT(0);
        }
        __syncthreads();

        const uint32_t stg = sb + buf * STAGE_BYTES;
#pragma unroll
        for (int ks = 0; ks < 2; ++ks) {
            // B fragments (single fp16, persist across i loop): 8 regs
            uint32_t bf[4][2];
#pragma unroll
            for (int j2 = 0; j2 < 2; ++j2) {
                const int nr = b_row0 + j2 * 16;
                const uint32_t off = (uint32_t)(nr * PADK + ks * 16 + b_colb) * 2;
                uint32_t t[4];
                LDSM4(t, stg + SOFF_B + off);
                bf[2 * j2][0] = t[0]; bf[2 * j2][1] = t[1];
                bf[2 * j2 + 1][0] = t[2]; bf[2 * j2 + 1][1] = t[3];
            }
            // A fragments streamed per i
#pragma unroll
            for (int i = 0; i < 4; ++i) {
                uint32_t ah[4], al[4];
                const uint32_t off = (uint32_t)((a_row + i * 16) * PADK + ks * 16 + a_colb) * 2;
                LDSM4(ah, stg + SOFF_AHI + off);
                LDSM4(al, stg + SOFF_ALO + off);
#pragma unroll
                for (int j = 0; j < 4; ++j) {
                    MMA_F16(acc[i][j], ah, bf[j]);   // hi * b
                    MMA_F16(acc[i][j], al, bf[j]);   // lo * b
                }
            }
        }
        __syncthreads();
    }

    // ---- epilogue: direct STG with bias ----
#pragma unroll
    for (int j = 0; j < 4; ++j) {
        const int ncol = n0 + warp_n * 32 + j * 8 + (lane & 3) * 2;
        const float2 bb = *reinterpret_cast<const float2*>(bias + ncol);
#pragma unroll
        for (int i = 0; i < 4; ++i) {
            const int row0 = m0 + warp_m * 64 + i * 16 + (lane >> 2);
            float2 v0 = make_float2(acc[i][j][0] + bb.x, acc[i][j][1] + bb.y);
            float2 v1 = make_float2(acc[i][j][2] + bb.x, acc[i][j][3] + bb.y);
            *reinterpret_cast<float2*>(O + (size_t)row0 * D + ncol) = v0;
            *reinterpret_cast<float2*>(O + (size_t)(row0 + 8) * D + ncol) = v1;
        }
    }
}

// ---------------- attention v3: 8 lanes/token, 4 tokens/warp, 2 iters ----------------
__global__ __launch_bounds__(256) void attn_kernel(
    const float* __restrict__ Er,
    const int*   __restrict__ layer_p,
    float* __restrict__ out,
    float* __restrict__ attn_out)
{
    const int wlocal = threadIdx.x >> 5;
    const int lane = threadIdx.x & 31;
    const int gw = blockIdx.x * 8 + wlocal;    // 16384 warps
    const int li = lane & 7;       // lane within 8-lane token group
    const int g  = lane >> 3;      // token group 0..3

    const int NCH = SEQ / 8;       // 512 t-chunks per (b,h)
    const int tc = gw & (NCH - 1);
    const int h  = (gw >> 9) & (NH - 1);
    const int b  = gw >> 12;

    const int dil = 1 << layer_p[0];
    const int shift_tab[8] = {0, 0, 0, 0, -2, -1, 1, 2};
    const int s = shift_tab[h];

    // preload Er fragment: this lane's 8 head-dims x 5 windows (t-independent)
    float erf[8][5];
#pragma unroll
    for (int k = 0; k < 8; ++k)
#pragma unroll
        for (int w = 0; w < WN; ++w)
            erf[k][w] = Er[(size_t)(h * HD + li * 8 + k) * WN + w];

    const float* Qb = g_qkv;
    const float* Kb = g_qkv + (size_t)MTOT * D;
    const float* Vb = g_qkv + 2ull * MTOT * D;
    const size_t rowbase = (size_t)b * SEQ;
    const int dcol = h * HD + li * 8;

#pragma unroll
    for (int it = 0; it < 2; ++it) {
        const int t = tc * 8 + it * 4 + g;
        const size_t qoff = (rowbase + t) * D + dcol;
        const float4 q0 = *reinterpret_cast<const float4*>(Qb + qoff);
        const float4 q1 = *reinterpret_cast<const float4*>(Qb + qoff + 4);

        float lg[WN];
        bool valid[WN];
        int tks[WN];
#pragma unroll
        for (int w = 0; w < WN; ++w) {
            const int tt = t + dil * (s + w - 2);
            const bool ok = (tt >= 0) && (tt < SEQ);
            valid[w] = ok;
            tks[w] = tt;
            float part = q0.x * erf[0][w] + q0.y * erf[1][w] + q0.z * erf[2][w] + q0.w * erf[3][w]
                       + q1.x * erf[4][w] + q1.y * erf[5][w] + q1.z * erf[6][w] + q1.w * erf[7][w];
            if (ok) {
                const size_t koff = (rowbase + tt) * D + dcol;
                const float4 k0 = *reinterpret_cast<const float4*>(Kb + koff);
                const float4 k1 = *reinterpret_cast<const float4*>(Kb + koff + 4);
                part += q0.x * k0.x + q0.y * k0.y + q0.z * k0.z + q0.w * k0.w
                      + q1.x * k1.x + q1.y * k1.y + q1.z * k1.z + q1.w * k1.w;
            }
            part += __shfl_xor_sync(0xffffffffu, part, 1);
            part += __shfl_xor_sync(0xffffffffu, part, 2);
            part += __shfl_xor_sync(0xffffffffu, part, 4);
            lg[w] = ok ? part * 0.125f : -1e30f;
        }

        float mx = lg[0];
#pragma unroll
        for (int w = 1; w < WN; w++) mx = fmaxf(mx, lg[w]);
        float p[WN];
        float sum = 0.f;
#pragma unroll
        for (int w = 0; w < WN; w++) {
            p[w] = valid[w] ? __expf(lg[w] - mx) : 0.f;
            sum += p[w];
        }
        const float inv = 1.f / sum;

        float4 a0 = make_float4(0.f, 0.f, 0.f, 0.f);
        float4 a1 = make_float4(0.f, 0.f, 0.f, 0.f);
#pragma unroll
        for (int w = 0; w < WN; w++) {
            if (valid[w]) {
                const float a = p[w] * inv;
                const size_t voff = (rowbase + tks[w]) * D + dcol;
                const float4 v0 = *reinterpret_cast<const float4*>(Vb + voff);
                const float4 v1 = *reinterpret_cast<const float4*>(Vb + voff + 4);
                a0.x = fmaf(a, v0.x, a0.x); a0.y = fmaf(a, v0.y, a0.y);
                a0.z = fmaf(a, v0.z, a0.z); a0.w = fmaf(a, v0.w, a0.w);
                a1.x = fmaf(a, v1.x, a1.x); a1.y = fmaf(a, v1.y, a1.y);
                a1.z = fmaf(a, v1.z, a1.z); a1.w = fmaf(a, v1.w, a1.w);
            }
        }
        *reinterpret_cast<float4*>(out + qoff) = a0;
        *reinterpret_cast<float4*>(out + qoff + 4) = a1;

        if (attn_out != nullptr && li < WN) {
            float a = p[0];
            if (li == 1) a = p[1];
            else if (li == 2) a = p[2];
            else if (li == 3) a = p[3];
            else if (li == 4) a = p[4];
            attn_out[((size_t)((b * NH + h) * SEQ + t)) * WN + li] = a * inv;
        }
    }
}

// ---------------------------------------------------------------------------
extern "C" void kernel_launch(void* const* d_in, const int* in_sizes, int n_in,
                              void* d_out, int out_size)
{
    (void)in_sizes; (void)n_in;
    const float* X  = (const float*)d_in[0];
    const float* Wq = (const float*)d_in[1];
    const float* bq = (const float*)d_in[2];
    const float* Wk = (const float*)d_in[3];
    const float* bk = (const float*)d_in[4];
    const float* Wv = (const float*)d_in[5];
    const float* bv = (const float*)d_in[6];
    const float* Er = (const float*)d_in[7];
    const int* layer = (const int*)d_in[8];

    float* out = (float*)d_out;
    float* attn_out = nullptr;
    const long long OUTN = (long long)MTOT * D;
    const long long ATTN = (long long)BATCH * NH * SEQ * WN;
    if ((long long)out_size >= OUTN + ATTN) attn_out = out + OUTN;

    static bool attr_set = false;
    if (!attr_set) {
        cudaFuncSetAttribute(qkv_gemm_mma, cudaFuncAttributeMaxDynamicSharedMemorySize, GEMM_SMEM);
        attr_set = true;
    }

    convert_x<<<(MTOT * D / 4) / 256, 256>>>(X);
    convert_w<<<(3 * D * D) / 256, 256>>>(Wq, Wk, Wv);

    dim3 grid(MTOT / BM, D / BN, 3);
    qkv_gemm_mma<<<grid, 256, GEMM_SMEM>>>(bq, bk, bv);

    const int nblocks = (BATCH * NH * (SEQ / 8)) / 8;   // 2048 blocks
    attn_kernel<<<nblocks, 256>>>(Er, layer, out, attn_out);
}

// round 7
// speedup vs baseline: 2.0358x; 1.4024x over previous
#include <cuda_runtime.h>
#include <cuda_fp16.h>
#include <cstdint>

#define D     512
#define NH    8
#define HD    64
#define WN    5
#define BATCH 4
#define SEQ   4096
#define MTOT  (BATCH * SEQ)

// ---------------- scratch (static device allocations) ----------------
__device__ float  g_qkv[3ull * MTOT * D];      // q,k,v fp32
__device__ __half g_X[(size_t)MTOT * D];       // X fp16
__device__ __half g_W[3ull * D * D];           // transposed: [n][k], fp16

// ---------------- PTX helpers ----------------
__device__ __forceinline__ uint32_t smem_u32(const void* p) {
    uint32_t a;
    asm("{ .reg .u64 t; cvta.to.shared.u64 t, %1; cvt.u32.u64 %0, t; }" : "=r"(a) : "l"(p));
    return a;
}
__device__ __forceinline__ void cp16(uint32_t dst, const void* src) {
    asm volatile("cp.async.cg.shared.global [%0], [%1], 16;" :: "r"(dst), "l"(src));
}
#define CP_COMMIT() asm volatile("cp.async.commit_group;" ::: "memory")
#define CP_WAIT(n)  asm volatile("cp.async.wait_group %0;" :: "n"(n) : "memory")

#define LDSM4(r, addr) \
    asm volatile("ldmatrix.sync.aligned.m8n8.x4.shared.b16 {%0,%1,%2,%3}, [%4];" \
        : "=r"((r)[0]), "=r"((r)[1]), "=r"((r)[2]), "=r"((r)[3]) : "r"(addr))

#define MMA_F16(c, a, b) \
    asm volatile("mma.sync.aligned.m16n8k16.row.col.f32.f16.f16.f32 " \
        "{%0,%1,%2,%3},{%4,%5,%6,%7},{%8,%9},{%0,%1,%2,%3};" \
        : "+f"((c)[0]), "+f"((c)[1]), "+f"((c)[2]), "+f"((c)[3]) \
        : "r"((a)[0]), "r"((a)[1]), "r"((a)[2]), "r"((a)[3]), "r"((b)[0]), "r"((b)[1]))

// ---------------- conversions ----------------
__global__ __launch_bounds__(256) void convert_x(const float* __restrict__ X) {
    size_t i = (size_t)blockIdx.x * 256 + threadIdx.x;   // float4 index
    float4 v = reinterpret_cast<const float4*>(X)[i];
    __half2 h0 = make_half2(__float2half_rn(v.x), __float2half_rn(v.y));
    __half2 h1 = make_half2(__float2half_rn(v.z), __float2half_rn(v.w));
    uint2 hh;
    hh.x = *reinterpret_cast<uint32_t*>(&h0);
    hh.y = *reinterpret_cast<uint32_t*>(&h1);
    reinterpret_cast<uint2*>(g_X)[i] = hh;
}

__global__ __launch_bounds__(256) void convert_w(const float* __restrict__ Wq,
                                                 const float* __restrict__ Wk,
                                                 const float* __restrict__ Wv) {
    int idx = blockIdx.x * 256 + threadIdx.x;   // < 3*512*512
    int z = idx >> 18;
    int r = idx & 262143;
    int k = r >> 9;
    int n = r & 511;
    const float* W = (z == 0) ? Wq : (z == 1 ? Wk : Wv);
    g_W[(size_t)z * D * D + (size_t)n * D + k] = __float2half_rn(W[(size_t)k * D + n]);
}

// ---------------- mma.sync GEMM (single-pass fp16) ----------------
#define BM 128
#define BN 128
#define BK 32
#define NKIT (D / BK)            // 16
#define PADK 40                  // row stride in fp16 (80 B rows)
#define TILE_BYTES (128 * PADK * 2)          // 10240
#define SOFF_A 0
#define SOFF_B TILE_BYTES
#define STAGE_BYTES (2 * TILE_BYTES)         // 20480
#define GEMM_SMEM (2 * STAGE_BYTES)          // 40960

__device__ __forceinline__ void load_stage(
    uint32_t sb, int stage, int m0, int n0, int kc,
    const __half* __restrict__ W, int tid)
{
    const uint32_t base = sb + stage * STAGE_BYTES;
#pragma unroll
    for (int p = 0; p < 2; ++p) {
        const int q = tid + p * 256;
        const int r = q >> 2, c = q & 3;
        const uint32_t doff = (uint32_t)(r * PADK + c * 8) * 2;
        cp16(base + SOFF_A + doff, g_X + (size_t)(m0 + r) * D + kc + c * 8);
        cp16(base + SOFF_B + doff, W + (size_t)(n0 + r) * D + kc + c * 8);
    }
}

__global__ __launch_bounds__(256, 2) void qkv_gemm_mma(
    const float* __restrict__ bq, const float* __restrict__ bk, const float* __restrict__ bv)
{
    extern __shared__ char smem[];
    const uint32_t sb = smem_u32(smem);

    const int tid = threadIdx.x;
    const int wid = tid >> 5;
    const int lane = tid & 31;
    const int warp_m = wid >> 2;      // 0..1
    const int warp_n = wid & 3;       // 0..3

    const int m0 = blockIdx.x * BM;
    const int n0 = blockIdx.y * BN;
    const int z = blockIdx.z;

    const __half* W = g_W + (size_t)z * D * D;
    float* O = g_qkv + (size_t)z * MTOT * D;
    const float* bias = (z == 0) ? bq : (z == 1 ? bk : bv);

    float acc[4][4][4];
#pragma unroll
    for (int i = 0; i < 4; i++)
#pragma unroll
        for (int j = 0; j < 4; j++)
#pragma unroll
            for (int e = 0; e < 4; e++) acc[i][j][e] = 0.f;

    load_stage(sb, 0, m0, n0, 0, W, tid);
    CP_COMMIT();

    const int a_row = warp_m * 64 + (lane & 15);
    const int a_colb = ((lane >> 4) << 3);
    const int b_row0 = warp_n * 32 + ((lane >> 4) << 3) + (lane & 7);
    const int b_colb = (((lane >> 3) & 1) << 3);

    for (int kt = 0; kt < NKIT; ++kt) {
        const int buf = kt & 1;
        if (kt + 1 < NKIT) {
            load_stage(sb, buf ^ 1, m0, n0, (kt + 1) * BK, W, tid);
            CP_COMMIT();
            CP_WAIT(1);
        } else {
            CP_WAIT(0);
        }
        __syncthreads();

        const uint32_t stg = sb + buf * STAGE_BYTES;
#pragma unroll
        for (int ks = 0; ks < 2; ++ks) {
            uint32_t bf[4][2];
#pragma unroll
            for (int j2 = 0; j2 < 2; ++j2) {
                const int nr = b_row0 + j2 * 16;
                const uint32_t off = (uint32_t)(nr * PADK + ks * 16 + b_colb) * 2;
                uint32_t t[4];
                LDSM4(t, stg + SOFF_B + off);
                bf[2 * j2][0] = t[0]; bf[2 * j2][1] = t[1];
                bf[2 * j2 + 1][0] = t[2]; bf[2 * j2 + 1][1] = t[3];
            }
#pragma unroll
            for (int i = 0; i < 4; ++i) {
                uint32_t af[4];
                const uint32_t off = (uint32_t)((a_row + i * 16) * PADK + ks * 16 + a_colb) * 2;
                LDSM4(af, stg + SOFF_A + off);
#pragma unroll
                for (int j = 0; j < 4; ++j)
                    MMA_F16(acc[i][j], af, bf[j]);
            }
        }
        __syncthreads();
    }

    // ---- epilogue: direct STG with bias ----
#pragma unroll
    for (int j = 0; j < 4; ++j) {
        const int ncol = n0 + warp_n * 32 + j * 8 + (lane & 3) * 2;
        const float2 bb = *reinterpret_cast<const float2*>(bias + ncol);
#pragma unroll
        for (int i = 0; i < 4; ++i) {
            const int row0 = m0 + warp_m * 64 + i * 16 + (lane >> 2);
            float2 v0 = make_float2(acc[i][j][0] + bb.x, acc[i][j][1] + bb.y);
            float2 v1 = make_float2(acc[i][j][2] + bb.x, acc[i][j][3] + bb.y);
            *reinterpret_cast<float2*>(O + (size_t)row0 * D + ncol) = v0;
            *reinterpret_cast<float2*>(O + (size_t)(row0 + 8) * D + ncol) = v1;
        }
    }
}

// ---------------- attention v4: 8 lanes/token, Er in smem ----------------
__global__ __launch_bounds__(256) void attn_kernel(
    const float* __restrict__ Er,
    const int*   __restrict__ layer_p,
    float* __restrict__ out,
    float* __restrict__ attn_out)
{
    __shared__ float sEr[WN][HD];    // 1.25 KB, shared by all warps (same head)

    const int wlocal = threadIdx.x >> 5;
    const int lane = threadIdx.x & 31;
    const int gw = blockIdx.x * 8 + wlocal;    // 16384 warps
    const int li = lane & 7;
    const int g  = lane >> 3;

    const int NCH = SEQ / 8;       // 512 t-chunks per (b,h)
    const int tc = gw & (NCH - 1);
    const int h  = (gw >> 9) & (NH - 1);
    const int b  = gw >> 12;

    // cooperative Er[h] load: 320 floats
    for (int i = threadIdx.x; i < WN * HD; i += 256) {
        const int w = i / HD, d = i % HD;
        sEr[w][d] = Er[(size_t)(h * HD + d) * WN + w];
    }
    __syncthreads();

    const int dil = 1 << layer_p[0];
    const int shift_tab[8] = {0, 0, 0, 0, -2, -1, 1, 2};
    const int s = shift_tab[h];

    const float* Qb = g_qkv;
    const float* Kb = g_qkv + (size_t)MTOT * D;
    const float* Vb = g_qkv + 2ull * MTOT * D;
    const size_t rowbase = (size_t)b * SEQ;
    const int dcol = h * HD + li * 8;

#pragma unroll
    for (int it = 0; it < 2; ++it) {
        const int t = tc * 8 + it * 4 + g;
        const size_t qoff = (rowbase + t) * D + dcol;
        const float4 q0 = *reinterpret_cast<const float4*>(Qb + qoff);
        const float4 q1 = *reinterpret_cast<const float4*>(Qb + qoff + 4);

        float lg[WN];
        bool valid[WN];
        int tks[WN];
#pragma unroll
        for (int w = 0; w < WN; ++w) {
            const int tt = t + dil * (s + w - 2);
            const bool ok = (tt >= 0) && (tt < SEQ);
            valid[w] = ok;
            tks[w] = tt;
            const float4 e0 = *reinterpret_cast<const float4*>(&sEr[w][li * 8]);
            const float4 e1 = *reinterpret_cast<const float4*>(&sEr[w][li * 8 + 4]);
            float part = q0.x * e0.x + q0.y * e0.y + q0.z * e0.z + q0.w * e0.w
                       + q1.x * e1.x + q1.y * e1.y + q1.z * e1.z + q1.w * e1.w;
            if (ok) {
                const size_t koff = (rowbase + tt) * D + dcol;
                const float4 k0 = *reinterpret_cast<const float4*>(Kb + koff);
                const float4 k1 = *reinterpret_cast<const float4*>(Kb + koff + 4);
                part += q0.x * k0.x + q0.y * k0.y + q0.z * k0.z + q0.w * k0.w
                      + q1.x * k1.x + q1.y * k1.y + q1.z * k1.z + q1.w * k1.w;
            }
            part += __shfl_xor_sync(0xffffffffu, part, 1);
            part += __shfl_xor_sync(0xffffffffu, part, 2);
            part += __shfl_xor_sync(0xffffffffu, part, 4);
            lg[w] = ok ? part * 0.125f : -1e30f;
        }

        float mx = lg[0];
#pragma unroll
        for (int w = 1; w < WN; w++) mx = fmaxf(mx, lg[w]);
        float p[WN];
        float sum = 0.f;
#pragma unroll
        for (int w = 0; w < WN; w++) {
            p[w] = valid[w] ? __expf(lg[w] - mx) : 0.f;
            sum += p[w];
        }
        const float inv = 1.f / sum;

        float4 a0 = make_float4(0.f, 0.f, 0.f, 0.f);
        float4 a1 = make_float4(0.f, 0.f, 0.f, 0.f);
#pragma unroll
        for (int w = 0; w < WN; w++) {
            if (valid[w]) {
                const float a = p[w] * inv;
                const size_t voff = (rowbase + tks[w]) * D + dcol;
                const float4 v0 = *reinterpret_cast<const float4*>(Vb + voff);
                const float4 v1 = *reinterpret_cast<const float4*>(Vb + voff + 4);
                a0.x = fmaf(a, v0.x, a0.x); a0.y = fmaf(a, v0.y, a0.y);
                a0.z = fmaf(a, v0.z, a0.z); a0.w = fmaf(a, v0.w, a0.w);
                a1.x = fmaf(a, v1.x, a1.x); a1.y = fmaf(a, v1.y, a1.y);
                a1.z = fmaf(a, v1.z, a1.z); a1.w = fmaf(a, v1.w, a1.w);
            }
        }
        *reinterpret_cast<float4*>(out + qoff) = a0;
        *reinterpret_cast<float4*>(out + qoff + 4) = a1;

        if (attn_out != nullptr && li < WN) {
            float a = p[0];
            if (li == 1) a = p[1];
            else if (li == 2) a = p[2];
            else if (li == 3) a = p[3];
            else if (li == 4) a = p[4];
            attn_out[((size_t)((b * NH + h) * SEQ + t)) * WN + li] = a * inv;
        }
    }
}

// ---------------------------------------------------------------------------
extern "C" void kernel_launch(void* const* d_in, const int* in_sizes, int n_in,
                              void* d_out, int out_size)
{
    (void)in_sizes; (void)n_in;
    const float* X  = (const float*)d_in[0];
    const float* Wq = (const float*)d_in[1];
    const float* bq = (const float*)d_in[2];
    const float* Wk = (const float*)d_in[3];
    const float* bk = (const float*)d_in[4];
    const float* Wv = (const float*)d_in[5];
    const float* bv = (const float*)d_in[6];
    const float* Er = (const float*)d_in[7];
    const int* layer = (const int*)d_in[8];

    float* out = (float*)d_out;
    float* attn_out = nullptr;
    const long long OUTN = (long long)MTOT * D;
    const long long ATTN = (long long)BATCH * NH * SEQ * WN;
    if ((long long)out_size >= OUTN + ATTN) attn_out = out + OUTN;

    static bool attr_set = false;
    if (!attr_set) {
        cudaFuncSetAttribute(qkv_gemm_mma, cudaFuncAttributeMaxDynamicSharedMemorySize, GEMM_SMEM);
        attr_set = true;
    }

    convert_x<<<(MTOT * D / 4) / 256, 256>>>(X);
    convert_w<<<(3 * D * D) / 256, 256>>>(Wq, Wk, Wv);

    dim3 grid(MTOT / BM, D / BN, 3);
    qkv_gemm_mma<<<grid, 256, GEMM_SMEM>>>(bq, bk, bv);

    const int nblocks = (BATCH * NH * (SEQ / 8)) / 8;   // 2048 blocks
    attn_kernel<<<nblocks, 256>>>(Er, layer, out, attn_out);
}

// round 8
// speedup vs baseline: 2.1802x; 1.0709x over previous
#include <cuda_runtime.h>
#include <cuda_fp16.h>
#include <cstdint>

#define D     512
#define NH    8
#define HD    64
#define WN    5
#define BATCH 4
#define SEQ   4096
#define MTOT  (BATCH * SEQ)

// ---------------- scratch (static device allocations) ----------------
__device__ float  g_qkv[3ull * MTOT * D];      // q,k,v fp32
__device__ __half g_X[(size_t)MTOT * D];       // X fp16
__device__ __half g_W[3ull * D * D];           // transposed: [n][k], fp16

// ---------------- PTX helpers ----------------
__device__ __forceinline__ uint32_t smem_u32(const void* p) {
    uint32_t a;
    asm("{ .reg .u64 t; cvta.to.shared.u64 t, %1; cvt.u32.u64 %0, t; }" : "=r"(a) : "l"(p));
    return a;
}
__device__ __forceinline__ void cp16(uint32_t dst, const void* src) {
    asm volatile("cp.async.cg.shared.global [%0], [%1], 16;" :: "r"(dst), "l"(src));
}
#define CP_COMMIT() asm volatile("cp.async.commit_group;" ::: "memory")
#define CP_WAIT(n)  asm volatile("cp.async.wait_group %0;" :: "n"(n) : "memory")

#define LDSM4(r, addr) \
    asm volatile("ldmatrix.sync.aligned.m8n8.x4.shared.b16 {%0,%1,%2,%3}, [%4];" \
        : "=r"((r)[0]), "=r"((r)[1]), "=r"((r)[2]), "=r"((r)[3]) : "r"(addr))

#define MMA_F16(c, a, b) \
    asm volatile("mma.sync.aligned.m16n8k16.row.col.f32.f16.f16.f32 " \
        "{%0,%1,%2,%3},{%4,%5,%6,%7},{%8,%9},{%0,%1,%2,%3};" \
        : "+f"((c)[0]), "+f"((c)[1]), "+f"((c)[2]), "+f"((c)[3]) \
        : "r"((a)[0]), "r"((a)[1]), "r"((a)[2]), "r"((a)[3]), "r"((b)[0]), "r"((b)[1]))

// ---------------- conversions ----------------
__global__ __launch_bounds__(256) void convert_x(const float* __restrict__ X) {
    size_t i = (size_t)blockIdx.x * 256 + threadIdx.x;   // float4 index
    float4 v = reinterpret_cast<const float4*>(X)[i];
    __half2 h0 = make_half2(__float2half_rn(v.x), __float2half_rn(v.y));
    __half2 h1 = make_half2(__float2half_rn(v.z), __float2half_rn(v.w));
    uint2 hh;
    hh.x = *reinterpret_cast<uint32_t*>(&h0);
    hh.y = *reinterpret_cast<uint32_t*>(&h1);
    reinterpret_cast<uint2*>(g_X)[i] = hh;
}

__global__ __launch_bounds__(256) void convert_w(const float* __restrict__ Wq,
                                                 const float* __restrict__ Wk,
                                                 const float* __restrict__ Wv) {
    int idx = blockIdx.x * 256 + threadIdx.x;   // < 3*512*512
    int z = idx >> 18;
    int r = idx & 262143;
    int k = r >> 9;
    int n = r & 511;
    const float* W = (z == 0) ? Wq : (z == 1 ? Wk : Wv);
    g_W[(size_t)z * D * D + (size_t)n * D + k] = __float2half_rn(W[(size_t)k * D + n]);
}

// ---------------- mma.sync GEMM (single-pass fp16) ----------------
#define BM 128
#define BN 128
#define BK 32
#define NKIT (D / BK)            // 16
#define PADK 40                  // row stride in fp16 (80 B rows)
#define TILE_BYTES (128 * PADK * 2)          // 10240
#define SOFF_A 0
#define SOFF_B TILE_BYTES
#define STAGE_BYTES (2 * TILE_BYTES)         // 20480
#define GEMM_SMEM (2 * STAGE_BYTES)          // 40960

__device__ __forceinline__ void load_stage(
    uint32_t sb, int stage, int m0, int n0, int kc,
    const __half* __restrict__ W, int tid)
{
    const uint32_t base = sb + stage * STAGE_BYTES;
#pragma unroll
    for (int p = 0; p < 2; ++p) {
        const int q = tid + p * 256;
        const int r = q >> 2, c = q & 3;
        const uint32_t doff = (uint32_t)(r * PADK + c * 8) * 2;
        cp16(base + SOFF_A + doff, g_X + (size_t)(m0 + r) * D + kc + c * 8);
        cp16(base + SOFF_B + doff, W + (size_t)(n0 + r) * D + kc + c * 8);
    }
}

__global__ __launch_bounds__(256, 2) void qkv_gemm_mma(
    const float* __restrict__ bq, const float* __restrict__ bk, const float* __restrict__ bv)
{
    extern __shared__ char smem[];
    const uint32_t sb = smem_u32(smem);

    const int tid = threadIdx.x;
    const int wid = tid >> 5;
    const int lane = tid & 31;
    const int warp_m = wid >> 2;      // 0..1
    const int warp_n = wid & 3;       // 0..3

    const int m0 = blockIdx.x * BM;
    const int n0 = blockIdx.y * BN;
    const int z = blockIdx.z;

    const __half* W = g_W + (size_t)z * D * D;
    float* O = g_qkv + (size_t)z * MTOT * D;
    const float* bias = (z == 0) ? bq : (z == 1 ? bk : bv);

    float acc[4][4][4];
#pragma unroll
    for (int i = 0; i < 4; i++)
#pragma unroll
        for (int j = 0; j < 4; j++)
#pragma unroll
            for (int e = 0; e < 4; e++) acc[i][j][e] = 0.f;

    load_stage(sb, 0, m0, n0, 0, W, tid);
    CP_COMMIT();

    const int a_row = warp_m * 64 + (lane & 15);
    const int a_colb = ((lane >> 4) << 3);
    const int b_row0 = warp_n * 32 + ((lane >> 4) << 3) + (lane & 7);
    const int b_colb = (((lane >> 3) & 1) << 3);

    for (int kt = 0; kt < NKIT; ++kt) {
        const int buf = kt & 1;
        if (kt + 1 < NKIT) {
            load_stage(sb, buf ^ 1, m0, n0, (kt + 1) * BK, W, tid);
            CP_COMMIT();
            CP_WAIT(1);
        } else {
            CP_WAIT(0);
        }
        __syncthreads();

        const uint32_t stg = sb + buf * STAGE_BYTES;
#pragma unroll
        for (int ks = 0; ks < 2; ++ks) {
            uint32_t bf[4][2];
#pragma unroll
            for (int j2 = 0; j2 < 2; ++j2) {
                const int nr = b_row0 + j2 * 16;
                const uint32_t off = (uint32_t)(nr * PADK + ks * 16 + b_colb) * 2;
                uint32_t t[4];
                LDSM4(t, stg + SOFF_B + off);
                bf[2 * j2][0] = t[0]; bf[2 * j2][1] = t[1];
                bf[2 * j2 + 1][0] = t[2]; bf[2 * j2 + 1][1] = t[3];
            }
#pragma unroll
            for (int i = 0; i < 4; ++i) {
                uint32_t af[4];
                const uint32_t off = (uint32_t)((a_row + i * 16) * PADK + ks * 16 + a_colb) * 2;
                LDSM4(af, stg + SOFF_A + off);
#pragma unroll
                for (int j = 0; j < 4; ++j)
                    MMA_F16(acc[i][j], af, bf[j]);
            }
        }
        __syncthreads();
    }

    // ---- epilogue: direct STG with bias ----
#pragma unroll
    for (int j = 0; j < 4; ++j) {
        const int ncol = n0 + warp_n * 32 + j * 8 + (lane & 3) * 2;
        const float2 bb = *reinterpret_cast<const float2*>(bias + ncol);
#pragma unroll
        for (int i = 0; i < 4; ++i) {
            const int row0 = m0 + warp_m * 64 + i * 16 + (lane >> 2);
            float2 v0 = make_float2(acc[i][j][0] + bb.x, acc[i][j][1] + bb.y);
            float2 v1 = make_float2(acc[i][j][2] + bb.x, acc[i][j][3] + bb.y);
            *reinterpret_cast<float2*>(O + (size_t)row0 * D + ncol) = v0;
            *reinterpret_cast<float2*>(O + (size_t)(row0 + 8) * D + ncol) = v1;
        }
    }
}

// ---------------- attention v5: 16 lanes/token, 2 tokens/warp ----------------
__global__ __launch_bounds__(256) void attn_kernel(
    const float* __restrict__ Er,
    const int*   __restrict__ layer_p,
    float* __restrict__ out,
    float* __restrict__ attn_out)
{
    __shared__ float sEr[WN][HD];    // 1.25 KB, shared by all warps (same head)

    const int wlocal = threadIdx.x >> 5;
    const int lane = threadIdx.x & 31;
    const int gw = blockIdx.x * 8 + wlocal;    // 65536 warps total
    const int li = lane & 15;      // dim group within 16-lane token segment
    const int g  = lane >> 4;      // token 0..1 within warp

    const int NCH = SEQ / 2;       // 2048 t-chunks per (b,h)
    const int tc = gw & (NCH - 1);
    const int h  = (gw >> 11) & (NH - 1);
    const int b  = gw >> 14;

    // cooperative Er[h] load: 320 floats
    for (int i = threadIdx.x; i < WN * HD; i += 256) {
        const int w = i / HD, d = i % HD;
        sEr[w][d] = Er[(size_t)(h * HD + d) * WN + w];
    }
    __syncthreads();

    const int dil = 1 << layer_p[0];
    const int shift_tab[8] = {0, 0, 0, 0, -2, -1, 1, 2};
    const int s = shift_tab[h];

    const float* Qb = g_qkv;
    const float* Kb = g_qkv + (size_t)MTOT * D;
    const float* Vb = g_qkv + 2ull * MTOT * D;
    const size_t rowbase = (size_t)b * SEQ;
    const int dcol = h * HD + li * 4;

    const int t = tc * 2 + g;
    const size_t qoff = (rowbase + t) * D + dcol;
    const float4 q0 = *reinterpret_cast<const float4*>(Qb + qoff);

    float lg[WN];
    bool valid[WN];
    int tks[WN];
#pragma unroll
    for (int w = 0; w < WN; ++w) {
        const int tt = t + dil * (s + w - 2);
        const bool ok = (tt >= 0) && (tt < SEQ);
        valid[w] = ok;
        tks[w] = tt;
        const float4 e0 = *reinterpret_cast<const float4*>(&sEr[w][li * 4]);
        float part = q0.x * e0.x + q0.y * e0.y + q0.z * e0.z + q0.w * e0.w;
        if (ok) {
            const float4 k0 = *reinterpret_cast<const float4*>(Kb + (rowbase + tt) * D + dcol);
            part += q0.x * k0.x + q0.y * k0.y + q0.z * k0.z + q0.w * k0.w;
        }
        part += __shfl_xor_sync(0xffffffffu, part, 1);
        part += __shfl_xor_sync(0xffffffffu, part, 2);
        part += __shfl_xor_sync(0xffffffffu, part, 4);
        part += __shfl_xor_sync(0xffffffffu, part, 8);
        lg[w] = ok ? part * 0.125f : -1e30f;
    }

    float mx = lg[0];
#pragma unroll
    for (int w = 1; w < WN; w++) mx = fmaxf(mx, lg[w]);
    float p[WN];
    float sum = 0.f;
#pragma unroll
    for (int w = 0; w < WN; w++) {
        p[w] = valid[w] ? __expf(lg[w] - mx) : 0.f;
        sum += p[w];
    }
    const float inv = 1.f / sum;

    float4 a0 = make_float4(0.f, 0.f, 0.f, 0.f);
#pragma unroll
    for (int w = 0; w < WN; w++) {
        if (valid[w]) {
            const float a = p[w] * inv;
            const float4 v0 = *reinterpret_cast<const float4*>(Vb + (rowbase + tks[w]) * D + dcol);
            a0.x = fmaf(a, v0.x, a0.x); a0.y = fmaf(a, v0.y, a0.y);
            a0.z = fmaf(a, v0.z, a0.z); a0.w = fmaf(a, v0.w, a0.w);
        }
    }
    *reinterpret_cast<float4*>(out + qoff) = a0;

    if (attn_out != nullptr && li < WN) {
        float a = p[0];
        if (li == 1) a = p[1];
        else if (li == 2) a = p[2];
        else if (li == 3) a = p[3];
        else if (li == 4) a = p[4];
        attn_out[((size_t)((b * NH + h) * SEQ + t)) * WN + li] = a * inv;
    }
}

// ---------------------------------------------------------------------------
extern "C" void kernel_launch(void* const* d_in, const int* in_sizes, int n_in,
                              void* d_out, int out_size)
{
    (void)in_sizes; (void)n_in;
    const float* X  = (const float*)d_in[0];
    const float* Wq = (const float*)d_in[1];
    const float* bq = (const float*)d_in[2];
    const float* Wk = (const float*)d_in[3];
    const float* bk = (const float*)d_in[4];
    const float* Wv = (const float*)d_in[5];
    const float* bv = (const float*)d_in[6];
    const float* Er = (const float*)d_in[7];
    const int* layer = (const int*)d_in[8];

    float* out = (float*)d_out;
    float* attn_out = nullptr;
    const long long OUTN = (long long)MTOT * D;
    const long long ATTN = (long long)BATCH * NH * SEQ * WN;
    if ((long long)out_size >= OUTN + ATTN) attn_out = out + OUTN;

    static bool attr_set = false;
    if (!attr_set) {
        cudaFuncSetAttribute(qkv_gemm_mma, cudaFuncAttributeMaxDynamicSharedMemorySize, GEMM_SMEM);
        attr_set = true;
    }

    convert_x<<<(MTOT * D / 4) / 256, 256>>>(X);
    convert_w<<<(3 * D * D) / 256, 256>>>(Wq, Wk, Wv);

    dim3 grid(MTOT / BM, D / BN, 3);
    qkv_gemm_mma<<<grid, 256, GEMM_SMEM>>>(bq, bk, bv);

    const int nblocks = (BATCH * NH * (SEQ / 2)) / 8;   // 8192 blocks
    attn_kernel<<<nblocks, 256>>>(Er, layer, out, attn_out);
}

// round 9
// speedup vs baseline: 2.4139x; 1.1072x over previous
#include <cuda_runtime.h>
#include <cuda_fp16.h>
#include <cstdint>

#define D     512
#define NH    8
#define HD    64
#define WN    5
#define BATCH 4
#define SEQ   4096
#define MTOT  (BATCH * SEQ)

// ---------------- scratch (static device allocations) ----------------
__device__ float  g_qkv[3ull * MTOT * D];      // q,k,v fp32
__device__ __half g_X[(size_t)MTOT * D];       // X fp16
__device__ __half g_W[3ull * D * D];           // transposed: [n][k], fp16

// ---------------- PTX helpers ----------------
__device__ __forceinline__ uint32_t smem_u32(const void* p) {
    uint32_t a;
    asm("{ .reg .u64 t; cvta.to.shared.u64 t, %1; cvt.u32.u64 %0, t; }" : "=r"(a) : "l"(p));
    return a;
}
__device__ __forceinline__ void cp16(uint32_t dst, const void* src) {
    asm volatile("cp.async.cg.shared.global [%0], [%1], 16;" :: "r"(dst), "l"(src));
}
#define CP_COMMIT() asm volatile("cp.async.commit_group;" ::: "memory")
#define CP_WAIT(n)  asm volatile("cp.async.wait_group %0;" :: "n"(n) : "memory")

#define LDSM4(r, addr) \
    asm volatile("ldmatrix.sync.aligned.m8n8.x4.shared.b16 {%0,%1,%2,%3}, [%4];" \
        : "=r"((r)[0]), "=r"((r)[1]), "=r"((r)[2]), "=r"((r)[3]) : "r"(addr))

#define MMA_F16(c, a, b) \
    asm volatile("mma.sync.aligned.m16n8k16.row.col.f32.f16.f16.f32 " \
        "{%0,%1,%2,%3},{%4,%5,%6,%7},{%8,%9},{%0,%1,%2,%3};" \
        : "+f"((c)[0]), "+f"((c)[1]), "+f"((c)[2]), "+f"((c)[3]) \
        : "r"((a)[0]), "r"((a)[1]), "r"((a)[2]), "r"((a)[3]), "r"((b)[0]), "r"((b)[1]))

// ---------------- fused conversions ----------------
#define NXBLK ((MTOT * D / 4) / 256)     // 8192 blocks for X
#define NWBLK ((3 * D * D) / 256)        // 3072 blocks for W

__global__ __launch_bounds__(256) void convert_all(
    const float* __restrict__ X,
    const float* __restrict__ Wq, const float* __restrict__ Wk, const float* __restrict__ Wv)
{
    const int bid = blockIdx.x;
    if (bid < NXBLK) {
        size_t i = (size_t)bid * 256 + threadIdx.x;   // float4 index
        float4 v = reinterpret_cast<const float4*>(X)[i];
        __half2 h0 = make_half2(__float2half_rn(v.x), __float2half_rn(v.y));
        __half2 h1 = make_half2(__float2half_rn(v.z), __float2half_rn(v.w));
        uint2 hh;
        hh.x = *reinterpret_cast<uint32_t*>(&h0);
        hh.y = *reinterpret_cast<uint32_t*>(&h1);
        reinterpret_cast<uint2*>(g_X)[i] = hh;
    } else {
        int idx = (bid - NXBLK) * 256 + threadIdx.x;  // < 3*512*512
        int z = idx >> 18;
        int r = idx & 262143;
        int k = r >> 9;
        int n = r & 511;
        const float* W = (z == 0) ? Wq : (z == 1 ? Wk : Wv);
        g_W[(size_t)z * D * D + (size_t)n * D + k] = __float2half_rn(W[(size_t)k * D + n]);
    }
}

// ---------------- mma.sync GEMM (single-pass fp16, BK=64) ----------------
#define BM 128
#define BN 128
#define BK 64
#define NKIT (D / BK)            // 8
#define PADK 72                  // row stride in fp16 (144 B rows -> conflict-free ldmatrix)
#define TILE_BYTES (128 * PADK * 2)          // 18432
#define SOFF_A 0
#define SOFF_B TILE_BYTES
#define STAGE_BYTES (2 * TILE_BYTES)         // 36864
#define GEMM_SMEM (2 * STAGE_BYTES)          // 73728

__device__ __forceinline__ void load_stage(
    uint32_t sb, int stage, int m0, int n0, int kc,
    const __half* __restrict__ W, int tid)
{
    const uint32_t base = sb + stage * STAGE_BYTES;
    // 128 rows x 8 chunks of 8 halves, per tile -> 1024 cp16 per tile
#pragma unroll
    for (int p = 0; p < 4; ++p) {
        const int q = tid + p * 256;
        const int r = q >> 3, c = q & 7;
        const uint32_t doff = (uint32_t)(r * PADK + c * 8) * 2;
        cp16(base + SOFF_A + doff, g_X + (size_t)(m0 + r) * D + kc + c * 8);
        cp16(base + SOFF_B + doff, W + (size_t)(n0 + r) * D + kc + c * 8);
    }
}

__global__ __launch_bounds__(256, 2) void qkv_gemm_mma(
    const float* __restrict__ bq, const float* __restrict__ bk, const float* __restrict__ bv)
{
    extern __shared__ char smem[];
    const uint32_t sb = smem_u32(smem);

    const int tid = threadIdx.x;
    const int wid = tid >> 5;
    const int lane = tid & 31;
    const int warp_m = wid >> 2;      // 0..1
    const int warp_n = wid & 3;       // 0..3

    const int m0 = blockIdx.x * BM;
    const int n0 = blockIdx.y * BN;
    const int z = blockIdx.z;

    const __half* W = g_W + (size_t)z * D * D;
    float* O = g_qkv + (size_t)z * MTOT * D;
    const float* bias = (z == 0) ? bq : (z == 1 ? bk : bv);

    float acc[4][4][4];
#pragma unroll
    for (int i = 0; i < 4; i++)
#pragma unroll
        for (int j = 0; j < 4; j++)
#pragma unroll
            for (int e = 0; e < 4; e++) acc[i][j][e] = 0.f;

    load_stage(sb, 0, m0, n0, 0, W, tid);
    CP_COMMIT();

    const int a_row = warp_m * 64 + (lane & 15);
    const int a_colb = ((lane >> 4) << 3);
    const int b_row0 = warp_n * 32 + ((lane >> 4) << 3) + (lane & 7);
    const int b_colb = (((lane >> 3) & 1) << 3);

    for (int kt = 0; kt < NKIT; ++kt) {
        const int buf = kt & 1;
        if (kt + 1 < NKIT) {
            load_stage(sb, buf ^ 1, m0, n0, (kt + 1) * BK, W, tid);
            CP_COMMIT();
            CP_WAIT(1);
        } else {
            CP_WAIT(0);
        }
        __syncthreads();

        const uint32_t stg = sb + buf * STAGE_BYTES;
#pragma unroll
        for (int ks = 0; ks < 4; ++ks) {
            uint32_t bf[4][2];
#pragma unroll
            for (int j2 = 0; j2 < 2; ++j2) {
                const int nr = b_row0 + j2 * 16;
                const uint32_t off = (uint32_t)(nr * PADK + ks * 16 + b_colb) * 2;
                uint32_t t[4];
                LDSM4(t, stg + SOFF_B + off);
                bf[2 * j2][0] = t[0]; bf[2 * j2][1] = t[1];
                bf[2 * j2 + 1][0] = t[2]; bf[2 * j2 + 1][1] = t[3];
            }
#pragma unroll
            for (int i = 0; i < 4; ++i) {
                uint32_t af[4];
                const uint32_t off = (uint32_t)((a_row + i * 16) * PADK + ks * 16 + a_colb) * 2;
                LDSM4(af, stg + SOFF_A + off);
#pragma unroll
                for (int j = 0; j < 4; ++j)
                    MMA_F16(acc[i][j], af, bf[j]);
            }
        }
        __syncthreads();
    }

    // ---- epilogue: direct STG with bias ----
#pragma unroll
    for (int j = 0; j < 4; ++j) {
        const int ncol = n0 + warp_n * 32 + j * 8 + (lane & 3) * 2;
        const float2 bb = *reinterpret_cast<const float2*>(bias + ncol);
#pragma unroll
        for (int i = 0; i < 4; ++i) {
            const int row0 = m0 + warp_m * 64 + i * 16 + (lane >> 2);
            float2 v0 = make_float2(acc[i][j][0] + bb.x, acc[i][j][1] + bb.y);
            float2 v1 = make_float2(acc[i][j][2] + bb.x, acc[i][j][3] + bb.y);
            *reinterpret_cast<float2*>(O + (size_t)row0 * D + ncol) = v0;
            *reinterpret_cast<float2*>(O + (size_t)(row0 + 8) * D + ncol) = v1;
        }
    }
}

// ---------------- attention v6: 16 lanes/token, 32-bit addressing ----------------
__global__ __launch_bounds__(256) void attn_kernel(
    const float* __restrict__ Er,
    const int*   __restrict__ layer_p,
    float* __restrict__ out,
    float* __restrict__ attn_out)
{
    __shared__ float sEr[WN][HD];    // 1.25 KB, shared by all warps (same head)

    const int wlocal = threadIdx.x >> 5;
    const int lane = threadIdx.x & 31;
    const int gw = blockIdx.x * 8 + wlocal;    // 65536 warps total
    const int li = lane & 15;      // dim group within 16-lane token segment
    const int g  = lane >> 4;      // token 0..1 within warp

    const int NCH = SEQ / 2;       // 2048 t-chunks per (b,h)
    const int tc = gw & (NCH - 1);
    const int h  = (gw >> 11) & (NH - 1);
    const int b  = gw >> 14;

    // cooperative Er[h] load: 320 floats
    for (int i = threadIdx.x; i < WN * HD; i += 256) {
        const int w = i / HD, d = i % HD;
        sEr[w][d] = Er[(size_t)(h * HD + d) * WN + w];
    }
    __syncthreads();

    const int dil = 1 << layer_p[0];
    // branch-free shift: h<4 -> 0; h=4..7 -> {-2,-1,1,2}
    const int s = (h < 4) ? 0 : ((h & 3) - 2 + (h >= 6));

    const float* Qb = g_qkv;
    const float* Kb = g_qkv + (size_t)MTOT * D;
    const float* Vb = g_qkv + 2ull * MTOT * D;

    const int t = tc * 2 + g;
    const uint32_t rowbase = (uint32_t)b * SEQ;
    const uint32_t dcol = (uint32_t)(h * HD + li * 4);
    const uint32_t qoff = (rowbase + (uint32_t)t) * D + dcol;
    const float4 q0 = *reinterpret_cast<const float4*>(Qb + qoff);

    float lg[WN];
    bool valid[WN];
    uint32_t koffs[WN];
#pragma unroll
    for (int w = 0; w < WN; ++w) {
        const int tt = t + dil * (s + w - 2);
        const bool ok = (tt >= 0) && (tt < SEQ);
        valid[w] = ok;
        koffs[w] = (rowbase + (uint32_t)tt) * D + dcol;
        const float4 e0 = *reinterpret_cast<const float4*>(&sEr[w][li * 4]);
        float part = q0.x * e0.x + q0.y * e0.y + q0.z * e0.z + q0.w * e0.w;
        if (ok) {
            const float4 k0 = *reinterpret_cast<const float4*>(Kb + koffs[w]);
            part += q0.x * k0.x + q0.y * k0.y + q0.z * k0.z + q0.w * k0.w;
        }
        part += __shfl_xor_sync(0xffffffffu, part, 1);
        part += __shfl_xor_sync(0xffffffffu, part, 2);
        part += __shfl_xor_sync(0xffffffffu, part, 4);
        part += __shfl_xor_sync(0xffffffffu, part, 8);
        lg[w] = ok ? part * 0.125f : -1e30f;
    }

    float mx = lg[0];
#pragma unroll
    for (int w = 1; w < WN; w++) mx = fmaxf(mx, lg[w]);
    float p[WN];
    float sum = 0.f;
#pragma unroll
    for (int w = 0; w < WN; w++) {
        p[w] = valid[w] ? __expf(lg[w] - mx) : 0.f;
        sum += p[w];
    }
    const float inv = 1.f / sum;

    float4 a0 = make_float4(0.f, 0.f, 0.f, 0.f);
#pragma unroll
    for (int w = 0; w < WN; w++) {
        if (valid[w]) {
            const float a = p[w] * inv;
            const float4 v0 = *reinterpret_cast<const float4*>(Vb + koffs[w]);
            a0.x = fmaf(a, v0.x, a0.x); a0.y = fmaf(a, v0.y, a0.y);
            a0.z = fmaf(a, v0.z, a0.z); a0.w = fmaf(a, v0.w, a0.w);
        }
    }
    *reinterpret_cast<float4*>(out + qoff) = a0;

    if (attn_out != nullptr && li < WN) {
        float a = p[0];
        if (li == 1) a = p[1];
        else if (li == 2) a = p[2];
        else if (li == 3) a = p[3];
        else if (li == 4) a = p[4];
        attn_out[((size_t)((b * NH + h) * SEQ + t)) * WN + li] = a * inv;
    }
}

// ---------------------------------------------------------------------------
extern "C" void kernel_launch(void* const* d_in, const int* in_sizes, int n_in,
                              void* d_out, int out_size)
{
    (void)in_sizes; (void)n_in;
    const float* X  = (const float*)d_in[0];
    const float* Wq = (const float*)d_in[1];
    const float* bq = (const float*)d_in[2];
    const float* Wk = (const float*)d_in[3];
    const float* bk = (const float*)d_in[4];
    const float* Wv = (const float*)d_in[5];
    const float* bv = (const float*)d_in[6];
    const float* Er = (const float*)d_in[7];
    const int* layer = (const int*)d_in[8];

    float* out = (float*)d_out;
    float* attn_out = nullptr;
    const long long OUTN = (long long)MTOT * D;
    const long long ATTN = (long long)BATCH * NH * SEQ * WN;
    if ((long long)out_size >= OUTN + ATTN) attn_out = out + OUTN;

    static bool attr_set = false;
    if (!attr_set) {
        cudaFuncSetAttribute(qkv_gemm_mma, cudaFuncAttributeMaxDynamicSharedMemorySize, GEMM_SMEM);
        attr_set = true;
    }

    convert_all<<<NXBLK + NWBLK, 256>>>(X, Wq, Wk, Wv);

    dim3 grid(MTOT / BM, D / BN, 3);
    qkv_gemm_mma<<<grid, 256, GEMM_SMEM>>>(bq, bk, bv);

    const int nblocks = (BATCH * NH * (SEQ / 2)) / 8;   // 8192 blocks
    attn_kernel<<<nblocks, 256>>>(Er, layer, out, attn_out);
}

// round 10
// speedup vs baseline: 2.5693x; 1.0644x over previous
#include <cuda_runtime.h>
#include <cuda_fp16.h>
#include <cstdint>

#define D     512
#define NH    8
#define HD    64
#define WN    5
#define BATCH 4
#define SEQ   4096
#define MTOT  (BATCH * SEQ)

// ---------------- scratch (static device allocations) ----------------
__device__ __half g_qkv[3ull * MTOT * D];      // q,k,v fp16
__device__ __half g_X[(size_t)MTOT * D];       // X fp16
__device__ __half g_W[3ull * D * D];           // transposed: [n][k], fp16

// ---------------- PTX helpers ----------------
__device__ __forceinline__ uint32_t smem_u32(const void* p) {
    uint32_t a;
    asm("{ .reg .u64 t; cvta.to.shared.u64 t, %1; cvt.u32.u64 %0, t; }" : "=r"(a) : "l"(p));
    return a;
}
__device__ __forceinline__ void cp16(uint32_t dst, const void* src) {
    asm volatile("cp.async.cg.shared.global [%0], [%1], 16;" :: "r"(dst), "l"(src));
}
#define CP_COMMIT() asm volatile("cp.async.commit_group;" ::: "memory")
#define CP_WAIT(n)  asm volatile("cp.async.wait_group %0;" :: "n"(n) : "memory")

#define LDSM4(r, addr) \
    asm volatile("ldmatrix.sync.aligned.m8n8.x4.shared.b16 {%0,%1,%2,%3}, [%4];" \
        : "=r"((r)[0]), "=r"((r)[1]), "=r"((r)[2]), "=r"((r)[3]) : "r"(addr))

#define MMA_F16(c, a, b) \
    asm volatile("mma.sync.aligned.m16n8k16.row.col.f32.f16.f16.f32 " \
        "{%0,%1,%2,%3},{%4,%5,%6,%7},{%8,%9},{%0,%1,%2,%3};" \
        : "+f"((c)[0]), "+f"((c)[1]), "+f"((c)[2]), "+f"((c)[3]) \
        : "r"((a)[0]), "r"((a)[1]), "r"((a)[2]), "r"((a)[3]), "r"((b)[0]), "r"((b)[1]))

// ---------------- fused conversions ----------------
#define NXBLK ((MTOT * D / 4) / 256)     // 8192 blocks for X
#define NWBLK ((3 * D * D) / 256)        // 3072 blocks for W

__global__ __launch_bounds__(256) void convert_all(
    const float* __restrict__ X,
    const float* __restrict__ Wq, const float* __restrict__ Wk, const float* __restrict__ Wv)
{
    const int bid = blockIdx.x;
    if (bid < NXBLK) {
        size_t i = (size_t)bid * 256 + threadIdx.x;   // float4 index
        float4 v = reinterpret_cast<const float4*>(X)[i];
        __half2 h0 = make_half2(__float2half_rn(v.x), __float2half_rn(v.y));
        __half2 h1 = make_half2(__float2half_rn(v.z), __float2half_rn(v.w));
        uint2 hh;
        hh.x = *reinterpret_cast<uint32_t*>(&h0);
        hh.y = *reinterpret_cast<uint32_t*>(&h1);
        reinterpret_cast<uint2*>(g_X)[i] = hh;
    } else {
        int idx = (bid - NXBLK) * 256 + threadIdx.x;  // < 3*512*512
        int z = idx >> 18;
        int r = idx & 262143;
        int k = r >> 9;
        int n = r & 511;
        const float* W = (z == 0) ? Wq : (z == 1 ? Wk : Wv);
        g_W[(size_t)z * D * D + (size_t)n * D + k] = __float2half_rn(W[(size_t)k * D + n]);
    }
}

// ---------------- mma.sync GEMM (single-pass fp16, BK=64, fp16 out) ----------------
#define BM 128
#define BN 128
#define BK 64
#define NKIT (D / BK)            // 8
#define PADK 72                  // row stride in fp16 (144 B rows -> conflict-free ldmatrix)
#define TILE_BYTES (128 * PADK * 2)          // 18432
#define SOFF_A 0
#define SOFF_B TILE_BYTES
#define STAGE_BYTES (2 * TILE_BYTES)         // 36864
#define GEMM_SMEM (2 * STAGE_BYTES)          // 73728

__device__ __forceinline__ void load_stage(
    uint32_t sb, int stage, int m0, int n0, int kc,
    const __half* __restrict__ W, int tid)
{
    const uint32_t base = sb + stage * STAGE_BYTES;
#pragma unroll
    for (int p = 0; p < 4; ++p) {
        const int q = tid + p * 256;
        const int r = q >> 3, c = q & 7;
        const uint32_t doff = (uint32_t)(r * PADK + c * 8) * 2;
        cp16(base + SOFF_A + doff, g_X + (size_t)(m0 + r) * D + kc + c * 8);
        cp16(base + SOFF_B + doff, W + (size_t)(n0 + r) * D + kc + c * 8);
    }
}

__global__ __launch_bounds__(256, 2) void qkv_gemm_mma(
    const float* __restrict__ bq, const float* __restrict__ bk, const float* __restrict__ bv)
{
    extern __shared__ char smem[];
    const uint32_t sb = smem_u32(smem);

    const int tid = threadIdx.x;
    const int wid = tid >> 5;
    const int lane = tid & 31;
    const int warp_m = wid >> 2;      // 0..1
    const int warp_n = wid & 3;       // 0..3

    const int m0 = blockIdx.x * BM;
    const int n0 = blockIdx.y * BN;
    const int z = blockIdx.z;

    const __half* W = g_W + (size_t)z * D * D;
    __half* O = g_qkv + (size_t)z * MTOT * D;
    const float* bias = (z == 0) ? bq : (z == 1 ? bk : bv);

    float acc[4][4][4];
#pragma unroll
    for (int i = 0; i < 4; i++)
#pragma unroll
        for (int j = 0; j < 4; j++)
#pragma unroll
            for (int e = 0; e < 4; e++) acc[i][j][e] = 0.f;

    load_stage(sb, 0, m0, n0, 0, W, tid);
    CP_COMMIT();

    const int a_row = warp_m * 64 + (lane & 15);
    const int a_colb = ((lane >> 4) << 3);
    const int b_row0 = warp_n * 32 + ((lane >> 4) << 3) + (lane & 7);
    const int b_colb = (((lane >> 3) & 1) << 3);

    for (int kt = 0; kt < NKIT; ++kt) {
        const int buf = kt & 1;
        if (kt + 1 < NKIT) {
            load_stage(sb, buf ^ 1, m0, n0, (kt + 1) * BK, W, tid);
            CP_COMMIT();
            CP_WAIT(1);
        } else {
            CP_WAIT(0);
        }
        __syncthreads();

        const uint32_t stg = sb + buf * STAGE_BYTES;
#pragma unroll
        for (int ks = 0; ks < 4; ++ks) {
            uint32_t bf[4][2];
#pragma unroll
            for (int j2 = 0; j2 < 2; ++j2) {
                const int nr = b_row0 + j2 * 16;
                const uint32_t off = (uint32_t)(nr * PADK + ks * 16 + b_colb) * 2;
                uint32_t t[4];
                LDSM4(t, stg + SOFF_B + off);
                bf[2 * j2][0] = t[0]; bf[2 * j2][1] = t[1];
                bf[2 * j2 + 1][0] = t[2]; bf[2 * j2 + 1][1] = t[3];
            }
#pragma unroll
            for (int i = 0; i < 4; ++i) {
                uint32_t af[4];
                const uint32_t off = (uint32_t)((a_row + i * 16) * PADK + ks * 16 + a_colb) * 2;
                LDSM4(af, stg + SOFF_A + off);
#pragma unroll
                for (int j = 0; j < 4; ++j)
                    MMA_F16(acc[i][j], af, bf[j]);
            }
        }
        __syncthreads();
    }

    // ---- epilogue: fp16 store with bias (bias added in f32) ----
#pragma unroll
    for (int j = 0; j < 4; ++j) {
        const int ncol = n0 + warp_n * 32 + j * 8 + (lane & 3) * 2;
        const float2 bb = *reinterpret_cast<const float2*>(bias + ncol);
#pragma unroll
        for (int i = 0; i < 4; ++i) {
            const int row0 = m0 + warp_m * 64 + i * 16 + (lane >> 2);
            __half2 v0 = __floats2half2_rn(acc[i][j][0] + bb.x, acc[i][j][1] + bb.y);
            __half2 v1 = __floats2half2_rn(acc[i][j][2] + bb.x, acc[i][j][3] + bb.y);
            *reinterpret_cast<__half2*>(O + (size_t)row0 * D + ncol) = v0;
            *reinterpret_cast<__half2*>(O + (size_t)(row0 + 8) * D + ncol) = v1;
        }
    }
}

// ---------------- attention v7: fp16 qkv, 8 lanes/token, 4 tokens/warp ----------------
__global__ __launch_bounds__(256) void attn_kernel(
    const float* __restrict__ Er,
    const int*   __restrict__ layer_p,
    float* __restrict__ out,
    float* __restrict__ attn_out)
{
    __shared__ float sEr[WN][HD];    // 1.25 KB, shared by all warps (same head)

    const int wlocal = threadIdx.x >> 5;
    const int lane = threadIdx.x & 31;
    const int gw = blockIdx.x * 8 + wlocal;    // 32768 warps total
    const int li = lane & 7;       // dim group within 8-lane token segment
    const int g  = lane >> 3;      // token 0..3 within warp

    const int NCH = SEQ / 4;       // 1024 t-chunks per (b,h)
    const int tc = gw & (NCH - 1);
    const int h  = (gw >> 10) & (NH - 1);
    const int b  = gw >> 13;

    // cooperative Er[h] load: 320 floats
    for (int i = threadIdx.x; i < WN * HD; i += 256) {
        const int w = i / HD, d = i % HD;
        sEr[w][d] = Er[(size_t)(h * HD + d) * WN + w];
    }
    __syncthreads();

    const int dil = 1 << layer_p[0];
    // branch-free shift: h<4 -> 0; h=4..7 -> {-2,-1,1,2}
    const int s = (h < 4) ? 0 : ((h & 3) - 2 + (h >= 6));

    const __half* Qb = g_qkv;
    const __half* Kb = g_qkv + (size_t)MTOT * D;
    const __half* Vb = g_qkv + 2ull * MTOT * D;

    const int t = tc * 4 + g;
    const uint32_t rowbase = (uint32_t)b * SEQ;
    const uint32_t dcol = (uint32_t)(h * HD + li * 8);
    const uint32_t qoff = (rowbase + (uint32_t)t) * D + dcol;   // element index

    // load q (8 halves) -> 8 floats
    const uint4 qr = *reinterpret_cast<const uint4*>(Qb + qoff);
    float qf[8];
    {
        float2 f0 = __half22float2(*reinterpret_cast<const __half2*>(&qr.x));
        float2 f1 = __half22float2(*reinterpret_cast<const __half2*>(&qr.y));
        float2 f2 = __half22float2(*reinterpret_cast<const __half2*>(&qr.z));
        float2 f3 = __half22float2(*reinterpret_cast<const __half2*>(&qr.w));
        qf[0] = f0.x; qf[1] = f0.y; qf[2] = f1.x; qf[3] = f1.y;
        qf[4] = f2.x; qf[5] = f2.y; qf[6] = f3.x; qf[7] = f3.y;
    }

    float lg[WN];
    bool valid[WN];
    uint32_t koffs[WN];
#pragma unroll
    for (int w = 0; w < WN; ++w) {
        const int tt = t + dil * (s + w - 2);
        const bool ok = (tt >= 0) && (tt < SEQ);
        valid[w] = ok;
        koffs[w] = (rowbase + (uint32_t)tt) * D + dcol;
        const float4 e0 = *reinterpret_cast<const float4*>(&sEr[w][li * 8]);
        const float4 e1 = *reinterpret_cast<const float4*>(&sEr[w][li * 8 + 4]);
        float part = qf[0] * e0.x + qf[1] * e0.y + qf[2] * e0.z + qf[3] * e0.w
                   + qf[4] * e1.x + qf[5] * e1.y + qf[6] * e1.z + qf[7] * e1.w;
        if (ok) {
            const uint4 kr = *reinterpret_cast<const uint4*>(Kb + koffs[w]);
            float2 k0 = __half22float2(*reinterpret_cast<const __half2*>(&kr.x));
            float2 k1 = __half22float2(*reinterpret_cast<const __half2*>(&kr.y));
            float2 k2 = __half22float2(*reinterpret_cast<const __half2*>(&kr.z));
            float2 k3 = __half22float2(*reinterpret_cast<const __half2*>(&kr.w));
            part += qf[0] * k0.x + qf[1] * k0.y + qf[2] * k1.x + qf[3] * k1.y
                  + qf[4] * k2.x + qf[5] * k2.y + qf[6] * k3.x + qf[7] * k3.y;
        }
        part += __shfl_xor_sync(0xffffffffu, part, 1);
        part += __shfl_xor_sync(0xffffffffu, part, 2);
        part += __shfl_xor_sync(0xffffffffu, part, 4);
        lg[w] = ok ? part * 0.125f : -1e30f;
    }

    float mx = lg[0];
#pragma unroll
    for (int w = 1; w < WN; w++) mx = fmaxf(mx, lg[w]);
    float p[WN];
    float sum = 0.f;
#pragma unroll
    for (int w = 0; w < WN; w++) {
        p[w] = valid[w] ? __expf(lg[w] - mx) : 0.f;
        sum += p[w];
    }
    const float inv = 1.f / sum;

    float a0[8] = {0.f, 0.f, 0.f, 0.f, 0.f, 0.f, 0.f, 0.f};
#pragma unroll
    for (int w = 0; w < WN; w++) {
        if (valid[w]) {
            const float a = p[w] * inv;
            const uint4 vr = *reinterpret_cast<const uint4*>(Vb + koffs[w]);
            float2 v0 = __half22float2(*reinterpret_cast<const __half2*>(&vr.x));
            float2 v1 = __half22float2(*reinterpret_cast<const __half2*>(&vr.y));
            float2 v2 = __half22float2(*reinterpret_cast<const __half2*>(&vr.z));
            float2 v3 = __half22float2(*reinterpret_cast<const __half2*>(&vr.w));
            a0[0] = fmaf(a, v0.x, a0[0]); a0[1] = fmaf(a, v0.y, a0[1]);
            a0[2] = fmaf(a, v1.x, a0[2]); a0[3] = fmaf(a, v1.y, a0[3]);
            a0[4] = fmaf(a, v2.x, a0[4]); a0[5] = fmaf(a, v2.y, a0[5]);
            a0[6] = fmaf(a, v3.x, a0[6]); a0[7] = fmaf(a, v3.y, a0[7]);
        }
    }
    *reinterpret_cast<float4*>(out + qoff) = make_float4(a0[0], a0[1], a0[2], a0[3]);
    *reinterpret_cast<float4*>(out + qoff + 4) = make_float4(a0[4], a0[5], a0[6], a0[7]);

    if (attn_out != nullptr && li < WN) {
        float a = p[0];
        if (li == 1) a = p[1];
        else if (li == 2) a = p[2];
        else if (li == 3) a = p[3];
        else if (li == 4) a = p[4];
        attn_out[((size_t)((b * NH + h) * SEQ + t)) * WN + li] = a * inv;
    }
}

// ---------------------------------------------------------------------------
extern "C" void kernel_launch(void* const* d_in, const int* in_sizes, int n_in,
                              void* d_out, int out_size)
{
    (void)in_sizes; (void)n_in;
    const float* X  = (const float*)d_in[0];
    const float* Wq = (const float*)d_in[1];
    const float* bq = (const float*)d_in[2];
    const float* Wk = (const float*)d_in[3];
    const float* bk = (const float*)d_in[4];
    const float* Wv = (const float*)d_in[5];
    const float* bv = (const float*)d_in[6];
    const float* Er = (const float*)d_in[7];
    const int* layer = (const int*)d_in[8];

    float* out = (float*)d_out;
    float* attn_out = nullptr;
    const long long OUTN = (long long)MTOT * D;
    const long long ATTN = (long long)BATCH * NH * SEQ * WN;
    if ((long long)out_size >= OUTN + ATTN) attn_out = out + OUTN;

    static bool attr_set = false;
    if (!attr_set) {
        cudaFuncSetAttribute(qkv_gemm_mma, cudaFuncAttributeMaxDynamicSharedMemorySize, GEMM_SMEM);
        attr_set = true;
    }

    convert_all<<<NXBLK + NWBLK, 256>>>(X, Wq, Wk, Wv);

    dim3 grid(MTOT / BM, D / BN, 3);
    qkv_gemm_mma<<<grid, 256, GEMM_SMEM>>>(bq, bk, bv);

    const int nblocks = (BATCH * NH * (SEQ / 4)) / 8;   // 4096 blocks
    attn_kernel<<<nblocks, 256>>>(Er, layer, out, attn_out);
}

// round 11
// speedup vs baseline: 2.6377x; 1.0266x over previous
#include <cuda_runtime.h>
#include <cuda_fp16.h>
#include <cstdint>

#define D     512
#define NH    8
#define HD    64
#define WN    5
#define BATCH 4
#define SEQ   4096
#define MTOT  (BATCH * SEQ)

// ---------------- scratch (static device allocations) ----------------
__device__ __half g_qkv[3ull * MTOT * D];      // q,k,v fp16
__device__ __half g_X[(size_t)MTOT * D];       // X fp16
__device__ __half g_W[3ull * D * D];           // transposed: [n][k], fp16

// ---------------- PTX helpers ----------------
__device__ __forceinline__ uint32_t smem_u32(const void* p) {
    uint32_t a;
    asm("{ .reg .u64 t; cvta.to.shared.u64 t, %1; cvt.u32.u64 %0, t; }" : "=r"(a) : "l"(p));
    return a;
}
__device__ __forceinline__ void cp16(uint32_t dst, const void* src) {
    asm volatile("cp.async.cg.shared.global [%0], [%1], 16;" :: "r"(dst), "l"(src));
}
#define CP_COMMIT() asm volatile("cp.async.commit_group;" ::: "memory")
#define CP_WAIT(n)  asm volatile("cp.async.wait_group %0;" :: "n"(n) : "memory")

#define LDSM4(r, addr) \
    asm volatile("ldmatrix.sync.aligned.m8n8.x4.shared.b16 {%0,%1,%2,%3}, [%4];" \
        : "=r"((r)[0]), "=r"((r)[1]), "=r"((r)[2]), "=r"((r)[3]) : "r"(addr))

#define MMA_F16(c, a, b) \
    asm volatile("mma.sync.aligned.m16n8k16.row.col.f32.f16.f16.f32 " \
        "{%0,%1,%2,%3},{%4,%5,%6,%7},{%8,%9},{%0,%1,%2,%3};" \
        : "+f"((c)[0]), "+f"((c)[1]), "+f"((c)[2]), "+f"((c)[3]) \
        : "r"((a)[0]), "r"((a)[1]), "r"((a)[2]), "r"((a)[3]), "r"((b)[0]), "r"((b)[1]))

// ---------------- fused conversions (4 items/thread for X) ----------------
#define NXBLK ((MTOT * D / 4) / 1024)    // 2048 blocks for X (4 float4 per thread)
#define NWBLK ((3 * D * D) / 256)        // 3072 blocks for W

__global__ __launch_bounds__(256) void convert_all(
    const float* __restrict__ X,
    const float* __restrict__ Wq, const float* __restrict__ Wk, const float* __restrict__ Wv)
{
    const int bid = blockIdx.x;
    if (bid < NXBLK) {
        const size_t base = (size_t)bid * 1024 + threadIdx.x;
        float4 v[4];
#pragma unroll
        for (int p = 0; p < 4; ++p)
            v[p] = reinterpret_cast<const float4*>(X)[base + p * 256];
#pragma unroll
        for (int p = 0; p < 4; ++p) {
            __half2 h0 = make_half2(__float2half_rn(v[p].x), __float2half_rn(v[p].y));
            __half2 h1 = make_half2(__float2half_rn(v[p].z), __float2half_rn(v[p].w));
            uint2 hh;
            hh.x = *reinterpret_cast<uint32_t*>(&h0);
            hh.y = *reinterpret_cast<uint32_t*>(&h1);
            reinterpret_cast<uint2*>(g_X)[base + p * 256] = hh;
        }
    } else {
        int idx = (bid - NXBLK) * 256 + threadIdx.x;  // < 3*512*512
        int z = idx >> 18;
        int r = idx & 262143;
        int k = r >> 9;
        int n = r & 511;
        const float* W = (z == 0) ? Wq : (z == 1 ? Wk : Wv);
        g_W[(size_t)z * D * D + (size_t)n * D + k] = __float2half_rn(W[(size_t)k * D + n]);
    }
}

// ---------------- mma.sync GEMM (single-pass fp16, BK=64, fp16 out) ----------------
#define BM 128
#define BN 128
#define BK 64
#define NKIT (D / BK)            // 8
#define PADK 72                  // row stride in fp16 (144 B rows -> conflict-free ldmatrix)
#define TILE_BYTES (128 * PADK * 2)          // 18432
#define SOFF_A 0
#define SOFF_B TILE_BYTES
#define STAGE_BYTES (2 * TILE_BYTES)         // 36864
#define GEMM_SMEM (2 * STAGE_BYTES)          // 73728

__device__ __forceinline__ void load_stage(
    uint32_t sb, int stage, int m0, int n0, int kc,
    const __half* __restrict__ W, int tid)
{
    const uint32_t base = sb + stage * STAGE_BYTES;
#pragma unroll
    for (int p = 0; p < 4; ++p) {
        const int q = tid + p * 256;
        const int r = q >> 3, c = q & 7;
        const uint32_t doff = (uint32_t)(r * PADK + c * 8) * 2;
        cp16(base + SOFF_A + doff, g_X + (size_t)(m0 + r) * D + kc + c * 8);
        cp16(base + SOFF_B + doff, W + (size_t)(n0 + r) * D + kc + c * 8);
    }
}

__global__ __launch_bounds__(256, 2) void qkv_gemm_mma(
    const float* __restrict__ bq, const float* __restrict__ bk, const float* __restrict__ bv)
{
    extern __shared__ char smem[];
    const uint32_t sb = smem_u32(smem);

    const int tid = threadIdx.x;
    const int wid = tid >> 5;
    const int lane = tid & 31;
    const int warp_m = wid >> 2;      // 0..1
    const int warp_n = wid & 3;       // 0..3

    const int m0 = blockIdx.x * BM;
    const int n0 = blockIdx.y * BN;
    const int z = blockIdx.z;

    const __half* W = g_W + (size_t)z * D * D;
    __half* O = g_qkv + (size_t)z * MTOT * D;
    const float* bias = (z == 0) ? bq : (z == 1 ? bk : bv);

    float acc[4][4][4];
#pragma unroll
    for (int i = 0; i < 4; i++)
#pragma unroll
        for (int j = 0; j < 4; j++)
#pragma unroll
            for (int e = 0; e < 4; e++) acc[i][j][e] = 0.f;

    load_stage(sb, 0, m0, n0, 0, W, tid);
    CP_COMMIT();

    const int a_row = warp_m * 64 + (lane & 15);
    const int a_colb = ((lane >> 4) << 3);
    const int b_row0 = warp_n * 32 + ((lane >> 4) << 3) + (lane & 7);
    const int b_colb = (((lane >> 3) & 1) << 3);

    for (int kt = 0; kt < NKIT; ++kt) {
        const int buf = kt & 1;
        if (kt + 1 < NKIT) {
            load_stage(sb, buf ^ 1, m0, n0, (kt + 1) * BK, W, tid);
            CP_COMMIT();
            CP_WAIT(1);
        } else {
            CP_WAIT(0);
        }
        __syncthreads();

        const uint32_t stg = sb + buf * STAGE_BYTES;
#pragma unroll
        for (int ks = 0; ks < 4; ++ks) {
            uint32_t bf[4][2];
#pragma unroll
            for (int j2 = 0; j2 < 2; ++j2) {
                const int nr = b_row0 + j2 * 16;
                const uint32_t off = (uint32_t)(nr * PADK + ks * 16 + b_colb) * 2;
                uint32_t t[4];
                LDSM4(t, stg + SOFF_B + off);
                bf[2 * j2][0] = t[0]; bf[2 * j2][1] = t[1];
                bf[2 * j2 + 1][0] = t[2]; bf[2 * j2 + 1][1] = t[3];
            }
#pragma unroll
            for (int i = 0; i < 4; ++i) {
                uint32_t af[4];
                const uint32_t off = (uint32_t)((a_row + i * 16) * PADK + ks * 16 + a_colb) * 2;
                LDSM4(af, stg + SOFF_A + off);
#pragma unroll
                for (int j = 0; j < 4; ++j)
                    MMA_F16(acc[i][j], af, bf[j]);
            }
        }
        __syncthreads();
    }

    // ---- epilogue: fp16 store with bias (bias added in f32) ----
#pragma unroll
    for (int j = 0; j < 4; ++j) {
        const int ncol = n0 + warp_n * 32 + j * 8 + (lane & 3) * 2;
        const float2 bb = *reinterpret_cast<const float2*>(bias + ncol);
#pragma unroll
        for (int i = 0; i < 4; ++i) {
            const int row0 = m0 + warp_m * 64 + i * 16 + (lane >> 2);
            __half2 v0 = __floats2half2_rn(acc[i][j][0] + bb.x, acc[i][j][1] + bb.y);
            __half2 v1 = __floats2half2_rn(acc[i][j][2] + bb.x, acc[i][j][3] + bb.y);
            *reinterpret_cast<__half2*>(O + (size_t)row0 * D + ncol) = v0;
            *reinterpret_cast<__half2*>(O + (size_t)(row0 + 8) * D + ncol) = v1;
        }
    }
}

// ---------------- attention v8: fp16 qkv, K+V loads in one MLP phase ----------------
__global__ __launch_bounds__(256) void attn_kernel(
    const float* __restrict__ Er,
    const int*   __restrict__ layer_p,
    float* __restrict__ out,
    float* __restrict__ attn_out)
{
    __shared__ float sEr[WN][HD];    // 1.25 KB, shared by all warps (same head)

    const int wlocal = threadIdx.x >> 5;
    const int lane = threadIdx.x & 31;
    const int gw = blockIdx.x * 8 + wlocal;    // 32768 warps total
    const int li = lane & 7;       // dim group within 8-lane token segment
    const int g  = lane >> 3;      // token 0..3 within warp

    const int NCH = SEQ / 4;       // 1024 t-chunks per (b,h)
    const int tc = gw & (NCH - 1);
    const int h  = (gw >> 10) & (NH - 1);
    const int b  = gw >> 13;

    // cooperative Er[h] load: 320 floats
    for (int i = threadIdx.x; i < WN * HD; i += 256) {
        const int w = i / HD, d = i % HD;
        sEr[w][d] = Er[(size_t)(h * HD + d) * WN + w];
    }
    __syncthreads();

    const int dil = 1 << layer_p[0];
    // branch-free shift: h<4 -> 0; h=4..7 -> {-2,-1,1,2}
    const int s = (h < 4) ? 0 : ((h & 3) - 2 + (h >= 6));

    const __half* Qb = g_qkv;
    const __half* Kb = g_qkv + (size_t)MTOT * D;
    const __half* Vb = g_qkv + 2ull * MTOT * D;

    const int t = tc * 4 + g;
    const uint32_t rowbase = (uint32_t)b * SEQ;
    const uint32_t dcol = (uint32_t)(h * HD + li * 8);
    const uint32_t qoff = (rowbase + (uint32_t)t) * D + dcol;   // element index

    // load q (8 halves) -> 8 floats
    const uint4 qr = *reinterpret_cast<const uint4*>(Qb + qoff);
    float qf[8];
    {
        float2 f0 = __half22float2(*reinterpret_cast<const __half2*>(&qr.x));
        float2 f1 = __half22float2(*reinterpret_cast<const __half2*>(&qr.y));
        float2 f2 = __half22float2(*reinterpret_cast<const __half2*>(&qr.z));
        float2 f3 = __half22float2(*reinterpret_cast<const __half2*>(&qr.w));
        qf[0] = f0.x; qf[1] = f0.y; qf[2] = f1.x; qf[3] = f1.y;
        qf[4] = f2.x; qf[5] = f2.y; qf[6] = f3.x; qf[7] = f3.y;
    }

    float lg[WN];
    bool valid[WN];
    uint4 vr[WN];
#pragma unroll
    for (int w = 0; w < WN; ++w) {
        const int tt = t + dil * (s + w - 2);
        const bool ok = (tt >= 0) && (tt < SEQ);
        valid[w] = ok;
        const uint32_t off = (rowbase + (uint32_t)tt) * D + dcol;
        const float4 e0 = *reinterpret_cast<const float4*>(&sEr[w][li * 8]);
        const float4 e1 = *reinterpret_cast<const float4*>(&sEr[w][li * 8 + 4]);
        float part = qf[0] * e0.x + qf[1] * e0.y + qf[2] * e0.z + qf[3] * e0.w
                   + qf[4] * e1.x + qf[5] * e1.y + qf[6] * e1.z + qf[7] * e1.w;
        if (ok) {
            const uint4 kr = *reinterpret_cast<const uint4*>(Kb + off);
            vr[w] = *reinterpret_cast<const uint4*>(Vb + off);   // prefetch V now
            float2 k0 = __half22float2(*reinterpret_cast<const __half2*>(&kr.x));
            float2 k1 = __half22float2(*reinterpret_cast<const __half2*>(&kr.y));
            float2 k2 = __half22float2(*reinterpret_cast<const __half2*>(&kr.z));
            float2 k3 = __half22float2(*reinterpret_cast<const __half2*>(&kr.w));
            part += qf[0] * k0.x + qf[1] * k0.y + qf[2] * k1.x + qf[3] * k1.y
                  + qf[4] * k2.x + qf[5] * k2.y + qf[6] * k3.x + qf[7] * k3.y;
        } else {
            vr[w] = make_uint4(0u, 0u, 0u, 0u);
        }
        part += __shfl_xor_sync(0xffffffffu, part, 1);
        part += __shfl_xor_sync(0xffffffffu, part, 2);
        part += __shfl_xor_sync(0xffffffffu, part, 4);
        lg[w] = ok ? part * 0.125f : -1e30f;
    }

    float mx = lg[0];
#pragma unroll
    for (int w = 1; w < WN; w++) mx = fmaxf(mx, lg[w]);
    float p[WN];
    float sum = 0.f;
#pragma unroll
    for (int w = 0; w < WN; w++) {
        p[w] = valid[w] ? __expf(lg[w] - mx) : 0.f;
        sum += p[w];
    }
    const float inv = 1.f / sum;

    float a0[8] = {0.f, 0.f, 0.f, 0.f, 0.f, 0.f, 0.f, 0.f};
#pragma unroll
    for (int w = 0; w < WN; w++) {
        const float a = p[w];    // scale by inv at the end
        float2 v0 = __half22float2(*reinterpret_cast<const __half2*>(&vr[w].x));
        float2 v1 = __half22float2(*reinterpret_cast<const __half2*>(&vr[w].y));
        float2 v2 = __half22float2(*reinterpret_cast<const __half2*>(&vr[w].z));
        float2 v3 = __half22float2(*reinterpret_cast<const __half2*>(&vr[w].w));
        a0[0] = fmaf(a, v0.x, a0[0]); a0[1] = fmaf(a, v0.y, a0[1]);
        a0[2] = fmaf(a, v1.x, a0[2]); a0[3] = fmaf(a, v1.y, a0[3]);
        a0[4] = fmaf(a, v2.x, a0[4]); a0[5] = fmaf(a, v2.y, a0[5]);
        a0[6] = fmaf(a, v3.x, a0[6]); a0[7] = fmaf(a, v3.y, a0[7]);
    }
    *reinterpret_cast<float4*>(out + qoff) =
        make_float4(a0[0] * inv, a0[1] * inv, a0[2] * inv, a0[3] * inv);
    *reinterpret_cast<float4*>(out + qoff + 4) =
        make_float4(a0[4] * inv, a0[5] * inv, a0[6] * inv, a0[7] * inv);

    if (attn_out != nullptr && li < WN) {
        float a = p[0];
        if (li == 1) a = p[1];
        else if (li == 2) a = p[2];
        else if (li == 3) a = p[3];
        else if (li == 4) a = p[4];
        attn_out[((size_t)((b * NH + h) * SEQ + t)) * WN + li] = a * inv;
    }
}

// ---------------------------------------------------------------------------
extern "C" void kernel_launch(void* const* d_in, const int* in_sizes, int n_in,
                              void* d_out, int out_size)
{
    (void)in_sizes; (void)n_in;
    const float* X  = (const float*)d_in[0];
    const float* Wq = (const float*)d_in[1];
    const float* bq = (const float*)d_in[2];
    const float* Wk = (const float*)d_in[3];
    const float* bk = (const float*)d_in[4];
    const float* Wv = (const float*)d_in[5];
    const float* bv = (const float*)d_in[6];
    const float* Er = (const float*)d_in[7];
    const int* layer = (const int*)d_in[8];

    float* out = (float*)d_out;
    float* attn_out = nullptr;
    const long long OUTN = (long long)MTOT * D;
    const long long ATTN = (long long)BATCH * NH * SEQ * WN;
    if ((long long)out_size >= OUTN + ATTN) attn_out = out + OUTN;

    static bool attr_set = false;
    if (!attr_set) {
        cudaFuncSetAttribute(qkv_gemm_mma, cudaFuncAttributeMaxDynamicSharedMemorySize, GEMM_SMEM);
        attr_set = true;
    }

    convert_all<<<NXBLK + NWBLK, 256>>>(X, Wq, Wk, Wv);

    dim3 grid(MTOT / BM, D / BN, 3);
    qkv_gemm_mma<<<grid, 256, GEMM_SMEM>>>(bq, bk, bv);

    const int nblocks = (BATCH * NH * (SEQ / 4)) / 8;   // 4096 blocks
    attn_kernel<<<nblocks, 256>>>(Er, layer, out, attn_out);
}